// round 2
// baseline (speedup 1.0000x reference)
#include <cuda_runtime.h>
#include <math.h>

#define B_  2
#define S_  2048
#define D_  1024
#define H_  16
#define HD_ 64
#define I_  4096
#define W_  256
#define TOK (B_*S_)

// -------- scratch (allocation-free rule: __device__ globals) --------
__device__ float g_xln[TOK*D_];
__device__ float g_q  [TOK*D_];
__device__ float g_k  [TOK*D_];
__device__ float g_v  [TOK*D_];
__device__ float g_ctx[TOK*D_];
__device__ float g_hid[TOK*D_];
__device__ float g_h1 [(size_t)TOK*I_];
__device__ float g_h3 [(size_t)TOK*I_];

// ==================== LayerNorm (1 block / token) ====================
__global__ void ln_kernel(const float* __restrict__ x,
                          const float* __restrict__ g,
                          const float* __restrict__ b,
                          float* __restrict__ y) {
    int t   = blockIdx.x;
    int tid = threadIdx.x;                    // 256 threads, 4 floats each
    const float4* xr = (const float4*)(x + (size_t)t * D_);
    float4 xv = xr[tid];

    __shared__ float rbuf[8];
    __shared__ float s_mean, s_rstd;

    float s = xv.x + xv.y + xv.z + xv.w;
    #pragma unroll
    for (int o = 16; o; o >>= 1) s += __shfl_xor_sync(~0u, s, o);
    if ((tid & 31) == 0) rbuf[tid >> 5] = s;
    __syncthreads();
    if (tid == 0) {
        float m = 0.f;
        #pragma unroll
        for (int i = 0; i < 8; i++) m += rbuf[i];
        s_mean = m * (1.0f / D_);
    }
    __syncthreads();
    float mean = s_mean;

    float dx = xv.x - mean, dy = xv.y - mean, dz = xv.z - mean, dw = xv.w - mean;
    float s2 = dx*dx + dy*dy + dz*dz + dw*dw;
    #pragma unroll
    for (int o = 16; o; o >>= 1) s2 += __shfl_xor_sync(~0u, s2, o);
    if ((tid & 31) == 0) rbuf[tid >> 5] = s2;
    __syncthreads();
    if (tid == 0) {
        float v = 0.f;
        #pragma unroll
        for (int i = 0; i < 8; i++) v += rbuf[i];
        s_rstd = rsqrtf(v * (1.0f / D_) + 1e-6f);
    }
    __syncthreads();
    float rstd = s_rstd;

    const float4 gv = ((const float4*)g)[tid];
    const float4 bv = ((const float4*)b)[tid];
    float4 out;
    out.x = dx * rstd * gv.x + bv.x;
    out.y = dy * rstd * gv.y + bv.y;
    out.z = dz * rstd * gv.z + bv.z;
    out.w = dw * rstd * gv.w + bv.w;
    ((float4*)(y + (size_t)t * D_))[tid] = out;
}

// ==================== RoPE v2: 1 block(32 thr) per (token, head) ====================
// double-precision angle math; pair (d, d+32), inv_freq = 10000^(-d/32)
__global__ void rope2_kernel(float* __restrict__ x) {
    int th = blockIdx.x;            // t * H + h
    int t  = th >> 4;
    int h  = th & (H_ - 1);
    int s  = t & (S_ - 1);          // position within sequence
    int d  = threadIdx.x;           // 0..31 (one pair per thread)

    double inv = exp(-(double)d * (log(10000.0) / 32.0));
    double ang = (double)s * inv;
    float c  = (float)cos(ang);
    float sn = (float)sin(ang);

    float* p = x + (size_t)t * D_ + h * HD_ + d;
    float x1 = p[0], x2 = p[32];
    p[0]  = x1 * c - x2 * sn;
    p[32] = x2 * c + x1 * sn;
}

// ==================== attention v2: 1 block(64 thr) per (b,h,q) ====================
// sequential, trivially-verifiable reductions
__global__ void attn2_kernel(const float* __restrict__ q,
                             const float* __restrict__ k,
                             const float* __restrict__ v,
                             float* __restrict__ o) {
    int qi = blockIdx.x, h = blockIdx.y, b = blockIdx.z;
    int tid = threadIdx.x;                     // 64 threads

    __shared__ float qs[64];
    __shared__ float sc[W_];
    __shared__ float s_max, s_sum;

    int j0 = qi - (W_ - 1); if (j0 < 0) j0 = 0;
    int nk = qi - j0 + 1;

    qs[tid] = q[(size_t)(b * S_ + qi) * D_ + h * HD_ + tid];
    __syncthreads();

    // scores for keys j0..qi
    for (int j = tid; j < nk; j += 64) {
        const float* kr = k + (size_t)(b * S_ + j0 + j) * D_ + h * HD_;
        float a = 0.f;
        #pragma unroll
        for (int d = 0; d < 64; d++) a = fmaf(qs[d], kr[d], a);
        sc[j] = a * 0.125f;                    // 1/sqrt(64)
    }
    __syncthreads();

    if (tid == 0) {
        float m = sc[0];
        for (int j = 1; j < nk; j++) m = fmaxf(m, sc[j]);
        s_max = m;
    }
    __syncthreads();

    for (int j = tid; j < nk; j += 64) sc[j] = expf(sc[j] - s_max);
    __syncthreads();

    if (tid == 0) {
        float s = 0.f;
        for (int j = 0; j < nk; j++) s += sc[j];
        s_sum = s;
    }
    __syncthreads();
    float inv = 1.0f / s_sum;

    // out[d] = sum_j w_j * v[j][d]   (tid == d, coalesced v reads)
    float acc = 0.f;
    for (int j = 0; j < nk; j++)
        acc = fmaf(sc[j], v[(size_t)(b * S_ + j0 + j) * D_ + h * HD_ + tid], acc);
    o[(size_t)(b * S_ + qi) * D_ + h * HD_ + tid] = acc * inv;
}

// ==================== SGEMM 128x128x16, 8x8/thread ====================
// MODE 0: C = A@B   MODE 1: C = A@B + X   MODE 2: C = silu(A@B) * X
template<int MODE>
__global__ void __launch_bounds__(256, 2)
sgemm(const float* __restrict__ A, const float* __restrict__ Bm,
      float* __restrict__ C, const float* __restrict__ X,
      int M, int N, int K) {
    __shared__ float As[16][128];
    __shared__ float Bs[16][128];

    int tid = threadIdx.x;
    int m0 = blockIdx.y * 128;
    int n0 = blockIdx.x * 128;
    int ty = tid >> 4, tx = tid & 15;

    float acc[8][8];
    #pragma unroll
    for (int i = 0; i < 8; i++)
        #pragma unroll
        for (int j = 0; j < 8; j++) acc[i][j] = 0.f;

    int arow = tid >> 1;
    int akb  = (tid & 1) * 8;
    int brow = tid >> 5;            // 0..7
    int bn   = (tid & 31) * 4;

    const float* Aptr = A  + (size_t)(m0 + arow) * K + akb;
    const float* Bptr = Bm + (size_t)brow * N + n0 + bn;

    for (int kt = 0; kt < K; kt += 16) {
        float4 a0 = *(const float4*)(Aptr + kt);
        float4 a1 = *(const float4*)(Aptr + kt + 4);
        float4 b0 = *(const float4*)(Bptr + (size_t)kt * N);
        float4 b1 = *(const float4*)(Bptr + (size_t)(kt + 8) * N);

        As[akb+0][arow] = a0.x; As[akb+1][arow] = a0.y;
        As[akb+2][arow] = a0.z; As[akb+3][arow] = a0.w;
        As[akb+4][arow] = a1.x; As[akb+5][arow] = a1.y;
        As[akb+6][arow] = a1.z; As[akb+7][arow] = a1.w;
        *(float4*)&Bs[brow  ][bn] = b0;
        *(float4*)&Bs[brow+8][bn] = b1;
        __syncthreads();

        #pragma unroll
        for (int kk = 0; kk < 16; ++kk) {
            float4 a0v = *(const float4*)&As[kk][ty * 4];
            float4 a1v = *(const float4*)&As[kk][64 + ty * 4];
            float4 b0v = *(const float4*)&Bs[kk][tx * 4];
            float4 b1v = *(const float4*)&Bs[kk][64 + tx * 4];
            float av[8] = {a0v.x, a0v.y, a0v.z, a0v.w, a1v.x, a1v.y, a1v.z, a1v.w};
            float bv[8] = {b0v.x, b0v.y, b0v.z, b0v.w, b1v.x, b1v.y, b1v.z, b1v.w};
            #pragma unroll
            for (int i = 0; i < 8; i++)
                #pragma unroll
                for (int j = 0; j < 8; j++)
                    acc[i][j] = fmaf(av[i], bv[j], acc[i][j]);
        }
        __syncthreads();
    }

    #pragma unroll
    for (int i = 0; i < 8; i++) {
        int r = m0 + ((i < 4) ? (ty * 4 + i) : (64 + ty * 4 + i - 4));
        #pragma unroll
        for (int j = 0; j < 8; j++) {
            int c = n0 + ((j < 4) ? (tx * 4 + j) : (64 + tx * 4 + j - 4));
            size_t off = (size_t)r * N + c;
            float val = acc[i][j];
            if (MODE == 1) val += X[off];
            else if (MODE == 2) {
                float sg = 1.0f / (1.0f + expf(-val));
                val = val * sg * X[off];
            }
            C[off] = val;
        }
    }
}

// ==================== launch ====================
extern "C" void kernel_launch(void* const* d_in, const int* in_sizes, int n_in,
                              void* d_out, int out_size) {
    const float* hidden = (const float*)d_in[0];
    const float* wq     = (const float*)d_in[1];
    const float* wk     = (const float*)d_in[2];
    const float* wv     = (const float*)d_in[3];
    const float* wo     = (const float*)d_in[4];
    const float* w1     = (const float*)d_in[5];
    const float* w2     = (const float*)d_in[6];
    const float* w3     = (const float*)d_in[7];
    const float* ln1_g  = (const float*)d_in[8];
    const float* ln1_b  = (const float*)d_in[9];
    const float* ln2_g  = (const float*)d_in[10];
    const float* ln2_b  = (const float*)d_in[11];
    float* out = (float*)d_out;

    float *xln, *q, *k, *v, *ctx, *hid, *h1, *h3;
    cudaGetSymbolAddress((void**)&xln, g_xln);
    cudaGetSymbolAddress((void**)&q,   g_q);
    cudaGetSymbolAddress((void**)&k,   g_k);
    cudaGetSymbolAddress((void**)&v,   g_v);
    cudaGetSymbolAddress((void**)&ctx, g_ctx);
    cudaGetSymbolAddress((void**)&hid, g_hid);
    cudaGetSymbolAddress((void**)&h1,  g_h1);
    cudaGetSymbolAddress((void**)&h3,  g_h3);

    dim3 gD(D_ / 128, TOK / 128);   // N=1024 GEMMs
    dim3 gI(I_ / 128, TOK / 128);   // N=4096 GEMMs

    // --- attention sub-block ---
    ln_kernel<<<TOK, 256>>>(hidden, ln1_g, ln1_b, xln);
    sgemm<0><<<gD, 256>>>(xln, wq, q, nullptr, TOK, D_, D_);
    sgemm<0><<<gD, 256>>>(xln, wk, k, nullptr, TOK, D_, D_);
    sgemm<0><<<gD, 256>>>(xln, wv, v, nullptr, TOK, D_, D_);

    rope2_kernel<<<TOK * H_, 32>>>(q);
    rope2_kernel<<<TOK * H_, 32>>>(k);

    attn2_kernel<<<dim3(S_, H_, B_), 64>>>(q, k, v, ctx);

    sgemm<1><<<gD, 256>>>(ctx, wo, hid, hidden, TOK, D_, D_);   // + residual

    // --- SwiGLU MLP sub-block ---
    ln_kernel<<<TOK, 256>>>(hid, ln2_g, ln2_b, xln);
    sgemm<0><<<gI, 256>>>(xln, w3, h3, nullptr, TOK, I_, D_);
    sgemm<2><<<gI, 256>>>(xln, w1, h1, h3, TOK, I_, D_);        // silu(x@w1)*h3
    sgemm<1><<<gD, 256>>>(h1, w2, out, hid, TOK, D_, I_);       // + residual
}

// round 4
// speedup vs baseline: 1.3375x; 1.3375x over previous
#include <cuda_runtime.h>
#include <cuda_bf16.h>
#include <math.h>
#include <stdint.h>

#define B_  2
#define S_  2048
#define D_  1024
#define H_  16
#define HD_ 64
#define I_  4096
#define W_  256
#define TOK (B_*S_)
#define QKV_LD 3072

// ==================== scratch (__device__ globals; no allocs) ====================
__device__ float g_qkv[(size_t)TOK*QKV_LD];
__device__ float g_hid[TOK*D_];
__device__ float g_h13[(size_t)TOK*2*I_];

__device__ __nv_bfloat16 g_xahi[TOK*D_];
__device__ __nv_bfloat16 g_xalo[TOK*D_];
__device__ __nv_bfloat16 g_cahi[TOK*D_];
__device__ __nv_bfloat16 g_calo[TOK*D_];
__device__ __nv_bfloat16 g_ghi[(size_t)TOK*I_];
__device__ __nv_bfloat16 g_glo[(size_t)TOK*I_];

// transposed + split weights: [N_rows, K] bf16
__device__ __nv_bfloat16 g_wqkvhi[3072*1024];
__device__ __nv_bfloat16 g_wqkvlo[3072*1024];
__device__ __nv_bfloat16 g_wothi[1024*1024];
__device__ __nv_bfloat16 g_wotlo[1024*1024];
__device__ __nv_bfloat16 g_w13hi[(size_t)8192*1024];
__device__ __nv_bfloat16 g_w13lo[(size_t)8192*1024];
__device__ __nv_bfloat16 g_w2thi[(size_t)1024*4096];
__device__ __nv_bfloat16 g_w2tlo[(size_t)1024*4096];

// ==================== helpers ====================
__device__ __forceinline__ uint32_t smem_u32(const void* p) {
    return (uint32_t)__cvta_generic_to_shared(p);
}
__device__ __forceinline__ void ldsm4(uint32_t* r, uint32_t a) {
    asm volatile("ldmatrix.sync.aligned.m8n8.x4.shared.b16 {%0,%1,%2,%3}, [%4];"
                 : "=r"(r[0]), "=r"(r[1]), "=r"(r[2]), "=r"(r[3]) : "r"(a));
}
__device__ __forceinline__ void mma16816(float* d, const uint32_t* a, const uint32_t* b) {
    asm volatile("mma.sync.aligned.m16n8k16.row.col.f32.bf16.bf16.f32 "
                 "{%0,%1,%2,%3}, {%4,%5,%6,%7}, {%8,%9}, {%0,%1,%2,%3};"
                 : "+f"(d[0]), "+f"(d[1]), "+f"(d[2]), "+f"(d[3])
                 : "r"(a[0]), "r"(a[1]), "r"(a[2]), "r"(a[3]), "r"(b[0]), "r"(b[1]));
}
__device__ __forceinline__ void cpa16(uint32_t s, const void* g) {
    asm volatile("cp.async.cg.shared.global [%0], [%1], 16;" :: "r"(s), "l"(g) : "memory");
}

// smem tile geometry: 128 rows x 32 halves, padded to 40 halves/row (80B, conflict-free)
#define LDS_  40
#define TILEB (128*LDS_*2)      // bytes per tile = 10240

// ==================== HMMA split-bf16 GEMM: C = A@B^T (+X) ====================
// A[hi/lo]: [M,K] bf16 row-major; B[hi/lo]: [N,K] bf16 row-major
// MODE 0: C = acc    MODE 1: C = acc + X
template<int MODE>
__global__ void __launch_bounds__(256, 1)
hgemm(const __nv_bfloat16* __restrict__ Ahi, const __nv_bfloat16* __restrict__ Alo,
      const __nv_bfloat16* __restrict__ Bhi, const __nv_bfloat16* __restrict__ Blo,
      float* __restrict__ C, const float* __restrict__ X, int K, int ldc) {
    extern __shared__ char smem[];
    uint32_t s0 = smem_u32(smem);

    int tid = threadIdx.x, lane = tid & 31, wid = tid >> 5;
    int m0 = blockIdx.y * 128, n0 = blockIdx.x * 128;
    int wm = wid & 1, wn = wid >> 1;     // 2 x 4 warps; warp tile 64(M) x 32(N)

    float acc[4][4][4];
    #pragma unroll
    for (int i = 0; i < 4; i++)
        #pragma unroll
        for (int j = 0; j < 4; j++)
            #pragma unroll
            for (int e = 0; e < 4; e++) acc[i][j][e] = 0.f;

    // per-thread load coords (512 uint4 per tile, 2 per thread)
    int r0l = (tid + 0)   >> 2, c0l = ((tid + 0)   & 3) * 8;
    int r1l = (tid + 256) >> 2, c1l = ((tid + 256) & 3) * 8;

    const __nv_bfloat16* gA[2] = {Ahi, Alo};
    const __nv_bfloat16* gB[2] = {Bhi, Blo};

    auto issue = [&](int buf, int kc) {
        #pragma unroll
        for (int a = 0; a < 2; a++) {
            uint32_t sa = s0 + (buf * 4 + a) * TILEB;
            cpa16(sa + (r0l * LDS_ + c0l) * 2, gA[a] + (size_t)(m0 + r0l) * K + kc + c0l);
            cpa16(sa + (r1l * LDS_ + c1l) * 2, gA[a] + (size_t)(m0 + r1l) * K + kc + c1l);
            uint32_t sb = s0 + (buf * 4 + 2 + a) * TILEB;
            cpa16(sb + (r0l * LDS_ + c0l) * 2, gB[a] + (size_t)(n0 + r0l) * K + kc + c0l);
            cpa16(sb + (r1l * LDS_ + c1l) * 2, gB[a] + (size_t)(n0 + r1l) * K + kc + c1l);
        }
        asm volatile("cp.async.commit_group;" ::: "memory");
    };

    // ldmatrix lane-address components
    int arow = wm * 64 + (lane & 15);            // + mi*16
    int acol = (lane & 16) ? 8 : 0;              // + ks*16
    int brow = wn * 32 + (lane & 7) + ((lane & 16) ? 8 : 0);   // + ni2*16
    int bcol = (lane & 8) ? 8 : 0;               // + ks*16

    int NC = K >> 5;
    issue(0, 0);

    for (int c = 0; c < NC; ++c) {
        if (c + 1 < NC) {
            issue((c + 1) & 1, (c + 1) << 5);
            asm volatile("cp.async.wait_group 1;" ::: "memory");
        } else {
            asm volatile("cp.async.wait_group 0;" ::: "memory");
        }
        __syncthreads();

        int buf = c & 1;
        uint32_t sAh = s0 + (buf * 4 + 0) * TILEB;
        uint32_t sAl = s0 + (buf * 4 + 1) * TILEB;
        uint32_t sBh = s0 + (buf * 4 + 2) * TILEB;
        uint32_t sBl = s0 + (buf * 4 + 3) * TILEB;

        #pragma unroll
        for (int ks = 0; ks < 2; ++ks) {
            uint32_t bh[2][4], bl[2][4];
            #pragma unroll
            for (int ni2 = 0; ni2 < 2; ++ni2) {
                uint32_t off = ((brow + ni2 * 16) * LDS_ + bcol + ks * 16) * 2;
                ldsm4(bh[ni2], sBh + off);
                ldsm4(bl[ni2], sBl + off);
            }
            #pragma unroll
            for (int mi = 0; mi < 4; ++mi) {
                uint32_t aoff = ((arow + mi * 16) * LDS_ + acol + ks * 16) * 2;
                uint32_t ah[4], al[4];
                ldsm4(ah, sAh + aoff);
                ldsm4(al, sAl + aoff);
                #pragma unroll
                for (int n8 = 0; n8 < 4; ++n8) {
                    const uint32_t* bph = &bh[n8 >> 1][(n8 & 1) * 2];
                    const uint32_t* bpl = &bl[n8 >> 1][(n8 & 1) * 2];
                    mma16816(acc[mi][n8], ah, bph);
                    mma16816(acc[mi][n8], ah, bpl);
                    mma16816(acc[mi][n8], al, bph);
                }
            }
        }
        __syncthreads();
    }

    // epilogue
    int rbase = m0 + wm * 64 + (lane >> 2);
    int cbase = n0 + wn * 32 + (lane & 3) * 2;
    #pragma unroll
    for (int mi = 0; mi < 4; ++mi) {
        #pragma unroll
        for (int half = 0; half < 2; ++half) {
            int row = rbase + mi * 16 + half * 8;
            float* crow = C + (size_t)row * ldc;
            const float* xrow = (MODE == 1) ? X + (size_t)row * ldc : nullptr;
            #pragma unroll
            for (int n8 = 0; n8 < 4; ++n8) {
                int col = cbase + n8 * 8;
                float2 v;
                v.x = acc[mi][n8][half * 2 + 0];
                v.y = acc[mi][n8][half * 2 + 1];
                if (MODE == 1) {
                    float2 xv = *(const float2*)(xrow + col);
                    v.x += xv.x; v.y += xv.y;
                }
                *(float2*)(crow + col) = v;
            }
        }
    }
}

// ==================== weight prep: W[K,N] fp32 -> hi/lo bf16 [roff+N rows, K] ====================
__global__ void prep_w(const float* __restrict__ W, __nv_bfloat16* __restrict__ hi,
                       __nv_bfloat16* __restrict__ lo, int N, int roff, int ldo) {
    __shared__ float t[32][33];
    int tx = threadIdx.x, ty = threadIdx.y;     // 32 x 8
    int n0 = blockIdx.x * 32, k0 = blockIdx.y * 32;
    #pragma unroll
    for (int i = 0; i < 32; i += 8)
        t[ty + i][tx] = W[(size_t)(k0 + ty + i) * N + n0 + tx];
    __syncthreads();
    #pragma unroll
    for (int i = 0; i < 32; i += 8) {
        float v = t[tx][ty + i];
        size_t o = (size_t)(roff + n0 + ty + i) * ldo + k0 + tx;
        __nv_bfloat16 h = __float2bfloat16(v);
        hi[o] = h;
        lo[o] = __float2bfloat16(v - __bfloat162float(h));
    }
}

// ==================== LayerNorm + hi/lo split (1 block / token) ====================
__global__ void ln_split(const float* __restrict__ x, const float* __restrict__ g,
                         const float* __restrict__ b, __nv_bfloat16* __restrict__ hi,
                         __nv_bfloat16* __restrict__ lo) {
    int t = blockIdx.x, tid = threadIdx.x;      // 256 thr, 4 floats each
    const float4* xr = (const float4*)(x + (size_t)t * D_);
    float4 xv = xr[tid];
    __shared__ float rbuf[8];
    __shared__ float s_mean, s_rstd;

    float s = xv.x + xv.y + xv.z + xv.w;
    #pragma unroll
    for (int o = 16; o; o >>= 1) s += __shfl_xor_sync(~0u, s, o);
    if ((tid & 31) == 0) rbuf[tid >> 5] = s;
    __syncthreads();
    if (tid == 0) {
        float m = 0.f;
        #pragma unroll
        for (int i = 0; i < 8; i++) m += rbuf[i];
        s_mean = m * (1.0f / D_);
    }
    __syncthreads();
    float mean = s_mean;
    float dx = xv.x - mean, dy = xv.y - mean, dz = xv.z - mean, dw = xv.w - mean;
    float s2 = dx*dx + dy*dy + dz*dz + dw*dw;
    #pragma unroll
    for (int o = 16; o; o >>= 1) s2 += __shfl_xor_sync(~0u, s2, o);
    if ((tid & 31) == 0) rbuf[tid >> 5] = s2;
    __syncthreads();
    if (tid == 0) {
        float v = 0.f;
        #pragma unroll
        for (int i = 0; i < 8; i++) v += rbuf[i];
        s_rstd = rsqrtf(v * (1.0f / D_) + 1e-6f);
    }
    __syncthreads();
    float rstd = s_rstd;
    const float4 gv = ((const float4*)g)[tid];
    const float4 bv = ((const float4*)b)[tid];
    float o0 = dx * rstd * gv.x + bv.x;
    float o1 = dy * rstd * gv.y + bv.y;
    float o2 = dz * rstd * gv.z + bv.z;
    float o3 = dw * rstd * gv.w + bv.w;
    size_t base = (size_t)t * D_ + tid * 4;
    __nv_bfloat16 h0 = __float2bfloat16(o0), h1 = __float2bfloat16(o1);
    __nv_bfloat16 h2 = __float2bfloat16(o2), h3 = __float2bfloat16(o3);
    hi[base+0]=h0; hi[base+1]=h1; hi[base+2]=h2; hi[base+3]=h3;
    lo[base+0]=__float2bfloat16(o0-__bfloat162float(h0));
    lo[base+1]=__float2bfloat16(o1-__bfloat162float(h1));
    lo[base+2]=__float2bfloat16(o2-__bfloat162float(h2));
    lo[base+3]=__float2bfloat16(o3-__bfloat162float(h3));
}

// ==================== swiglu + split ====================
__global__ void swiglu_split(const float* __restrict__ h13, __nv_bfloat16* __restrict__ ghi,
                             __nv_bfloat16* __restrict__ glo) {
    int i = blockIdx.x * 256 + threadIdx.x;     // TOK*I
    int row = i >> 12, col = i & (I_ - 1);
    float a = h13[(size_t)row * (2 * I_) + col];
    float b = h13[(size_t)row * (2 * I_) + I_ + col];
    float g = a / (1.0f + expf(-a)) * b;
    __nv_bfloat16 h = __float2bfloat16(g);
    ghi[i] = h;
    glo[i] = __float2bfloat16(g - __bfloat162float(h));
}

// ==================== RoPE (32 thr per (token, head)) ====================
__global__ void rope2_kernel(float* __restrict__ x, int ld) {
    int th = blockIdx.x;
    int t = th >> 4, h = th & (H_ - 1);
    int s = t & (S_ - 1);
    int d = threadIdx.x;
    double inv = exp(-(double)d * (log(10000.0) / 32.0));
    double ang = (double)s * inv;
    float c = (float)cos(ang), sn = (float)sin(ang);
    float* p = x + (size_t)t * ld + h * HD_ + d;
    float x1 = p[0], x2 = p[32];
    p[0]  = x1 * c - x2 * sn;
    p[32] = x2 * c + x1 * sn;
}

// ==================== sliding-window attention (out: hi/lo bf16) ====================
__global__ void attn2_kernel(const float* __restrict__ q, const float* __restrict__ k,
                             const float* __restrict__ v,
                             __nv_bfloat16* __restrict__ ohi, __nv_bfloat16* __restrict__ olo,
                             int ldin) {
    int qi = blockIdx.x, h = blockIdx.y, b = blockIdx.z;
    int tid = threadIdx.x;      // 64
    __shared__ float qs[64];
    __shared__ float sc[W_];
    __shared__ float s_max, s_sum;

    int j0 = qi - (W_ - 1); if (j0 < 0) j0 = 0;
    int nk = qi - j0 + 1;

    qs[tid] = q[(size_t)(b * S_ + qi) * ldin + h * HD_ + tid];
    __syncthreads();

    for (int j = tid; j < nk; j += 64) {
        const float* kr = k + (size_t)(b * S_ + j0 + j) * ldin + h * HD_;
        float a = 0.f;
        #pragma unroll
        for (int d = 0; d < 64; d++) a = fmaf(qs[d], kr[d], a);
        sc[j] = a * 0.125f;
    }
    __syncthreads();
    if (tid == 0) {
        float m = sc[0];
        for (int j = 1; j < nk; j++) m = fmaxf(m, sc[j]);
        s_max = m;
    }
    __syncthreads();
    for (int j = tid; j < nk; j += 64) sc[j] = expf(sc[j] - s_max);
    __syncthreads();
    if (tid == 0) {
        float s = 0.f;
        for (int j = 0; j < nk; j++) s += sc[j];
        s_sum = s;
    }
    __syncthreads();
    float inv = 1.0f / s_sum;
    float acc = 0.f;
    for (int j = 0; j < nk; j++)
        acc = fmaf(sc[j], v[(size_t)(b * S_ + j0 + j) * ldin + h * HD_ + tid], acc);
    float r = acc * inv;
    size_t o = (size_t)(b * S_ + qi) * D_ + h * HD_ + tid;
    __nv_bfloat16 hb = __float2bfloat16(r);
    ohi[o] = hb;
    olo[o] = __float2bfloat16(r - __bfloat162float(hb));
}

// ==================== launch ====================
extern "C" void kernel_launch(void* const* d_in, const int* in_sizes, int n_in,
                              void* d_out, int out_size) {
    const float* hidden = (const float*)d_in[0];
    const float* wq = (const float*)d_in[1];
    const float* wk = (const float*)d_in[2];
    const float* wv = (const float*)d_in[3];
    const float* wo = (const float*)d_in[4];
    const float* w1 = (const float*)d_in[5];
    const float* w2 = (const float*)d_in[6];
    const float* w3 = (const float*)d_in[7];
    const float* ln1_g = (const float*)d_in[8];
    const float* ln1_b = (const float*)d_in[9];
    const float* ln2_g = (const float*)d_in[10];
    const float* ln2_b = (const float*)d_in[11];
    float* out = (float*)d_out;

    float *qkv, *hid, *h13;
    __nv_bfloat16 *xahi, *xalo, *cahi, *calo, *ghi, *glo;
    __nv_bfloat16 *wqkvhi, *wqkvlo, *wothi, *wotlo, *w13hi, *w13lo, *w2thi, *w2tlo;
    cudaGetSymbolAddress((void**)&qkv, g_qkv);
    cudaGetSymbolAddress((void**)&hid, g_hid);
    cudaGetSymbolAddress((void**)&h13, g_h13);
    cudaGetSymbolAddress((void**)&xahi, g_xahi);
    cudaGetSymbolAddress((void**)&xalo, g_xalo);
    cudaGetSymbolAddress((void**)&cahi, g_cahi);
    cudaGetSymbolAddress((void**)&calo, g_calo);
    cudaGetSymbolAddress((void**)&ghi, g_ghi);
    cudaGetSymbolAddress((void**)&glo, g_glo);
    cudaGetSymbolAddress((void**)&wqkvhi, g_wqkvhi);
    cudaGetSymbolAddress((void**)&wqkvlo, g_wqkvlo);
    cudaGetSymbolAddress((void**)&wothi, g_wothi);
    cudaGetSymbolAddress((void**)&wotlo, g_wotlo);
    cudaGetSymbolAddress((void**)&w13hi, g_w13hi);
    cudaGetSymbolAddress((void**)&w13lo, g_w13lo);
    cudaGetSymbolAddress((void**)&w2thi, g_w2thi);
    cudaGetSymbolAddress((void**)&w2tlo, g_w2tlo);

    const int SMEM_DYN = 8 * TILEB;     // 81920 B: 2 buffers x 4 tiles
    cudaFuncSetAttribute(hgemm<0>, cudaFuncAttributeMaxDynamicSharedMemorySize, SMEM_DYN);
    cudaFuncSetAttribute(hgemm<1>, cudaFuncAttributeMaxDynamicSharedMemorySize, SMEM_DYN);

    dim3 tb(32, 8);
    prep_w<<<dim3(32, 32), tb>>>(wq, wqkvhi, wqkvlo, 1024, 0,    1024);
    prep_w<<<dim3(32, 32), tb>>>(wk, wqkvhi, wqkvlo, 1024, 1024, 1024);
    prep_w<<<dim3(32, 32), tb>>>(wv, wqkvhi, wqkvlo, 1024, 2048, 1024);
    prep_w<<<dim3(32, 32), tb>>>(wo, wothi,  wotlo,  1024, 0,    1024);
    prep_w<<<dim3(128, 32), tb>>>(w1, w13hi, w13lo, 4096, 0,    1024);
    prep_w<<<dim3(128, 32), tb>>>(w3, w13hi, w13lo, 4096, 4096, 1024);
    prep_w<<<dim3(32, 128), tb>>>(w2, w2thi, w2tlo, 1024, 0,    4096);

    // --- attention sub-block ---
    ln_split<<<TOK, 256>>>(hidden, ln1_g, ln1_b, xahi, xalo);
    hgemm<0><<<dim3(3072/128, TOK/128), 256, SMEM_DYN>>>(
        xahi, xalo, wqkvhi, wqkvlo, qkv, nullptr, 1024, QKV_LD);

    rope2_kernel<<<TOK * H_, 32>>>(qkv, QKV_LD);           // q
    rope2_kernel<<<TOK * H_, 32>>>(qkv + 1024, QKV_LD);    // k
    attn2_kernel<<<dim3(S_, H_, B_), 64>>>(qkv, qkv + 1024, qkv + 2048, cahi, calo, QKV_LD);

    hgemm<1><<<dim3(1024/128, TOK/128), 256, SMEM_DYN>>>(
        cahi, calo, wothi, wotlo, hid, hidden, 1024, D_);  // + residual

    // --- SwiGLU MLP sub-block ---
    ln_split<<<TOK, 256>>>(hid, ln2_g, ln2_b, xahi, xalo);
    hgemm<0><<<dim3(8192/128, TOK/128), 256, SMEM_DYN>>>(
        xahi, xalo, w13hi, w13lo, h13, nullptr, 1024, 2 * I_);

    swiglu_split<<<(TOK * I_) / 256, 256>>>(h13, ghi, glo);

    hgemm<1><<<dim3(1024/128, TOK/128), 256, SMEM_DYN>>>(
        ghi, glo, w2thi, w2tlo, out, hid, 4096, D_);       // + residual
}

// round 5
// speedup vs baseline: 5.5670x; 4.1623x over previous
#include <cuda_runtime.h>
#include <cuda_bf16.h>
#include <math.h>
#include <stdint.h>

#define B_  2
#define S_  2048
#define D_  1024
#define H_  16
#define HD_ 64
#define I_  4096
#define W_  256
#define TOK (B_*S_)
#define QKV_LD 3072

// ==================== scratch (__device__ globals; no allocs) ====================
__device__ float g_qkv[(size_t)TOK*QKV_LD];
__device__ float g_hid[TOK*D_];

__device__ __nv_bfloat16 g_xahi[TOK*D_];
__device__ __nv_bfloat16 g_xalo[TOK*D_];
__device__ __nv_bfloat16 g_cahi[TOK*D_];
__device__ __nv_bfloat16 g_calo[TOK*D_];
__device__ __nv_bfloat16 g_ghi[(size_t)TOK*I_];
__device__ __nv_bfloat16 g_glo[(size_t)TOK*I_];
__device__ __nv_bfloat16 g_qb[TOK*D_];   // [b,h,s,d] scaled by 0.125
__device__ __nv_bfloat16 g_kb[TOK*D_];   // [b,h,s,d]
__device__ __nv_bfloat16 g_vb[TOK*D_];   // [b,h,s,d]

// transposed + split weights: [N_rows, K] bf16 (w13: rows interleaved w1/w3)
__device__ __nv_bfloat16 g_wqkvhi[3072*1024];
__device__ __nv_bfloat16 g_wqkvlo[3072*1024];
__device__ __nv_bfloat16 g_wothi[1024*1024];
__device__ __nv_bfloat16 g_wotlo[1024*1024];
__device__ __nv_bfloat16 g_w13hi[(size_t)8192*1024];
__device__ __nv_bfloat16 g_w13lo[(size_t)8192*1024];
__device__ __nv_bfloat16 g_w2thi[(size_t)1024*4096];
__device__ __nv_bfloat16 g_w2tlo[(size_t)1024*4096];

// ==================== helpers ====================
__device__ __forceinline__ uint32_t smem_u32(const void* p) {
    return (uint32_t)__cvta_generic_to_shared(p);
}
__device__ __forceinline__ void ldsm4(uint32_t* r, uint32_t a) {
    asm volatile("ldmatrix.sync.aligned.m8n8.x4.shared.b16 {%0,%1,%2,%3}, [%4];"
                 : "=r"(r[0]), "=r"(r[1]), "=r"(r[2]), "=r"(r[3]) : "r"(a));
}
__device__ __forceinline__ void ldsm4t(uint32_t* r, uint32_t a) {
    asm volatile("ldmatrix.sync.aligned.m8n8.x4.trans.shared.b16 {%0,%1,%2,%3}, [%4];"
                 : "=r"(r[0]), "=r"(r[1]), "=r"(r[2]), "=r"(r[3]) : "r"(a));
}
__device__ __forceinline__ void mma16816(float* d, const uint32_t* a, const uint32_t* b) {
    asm volatile("mma.sync.aligned.m16n8k16.row.col.f32.bf16.bf16.f32 "
                 "{%0,%1,%2,%3}, {%4,%5,%6,%7}, {%8,%9}, {%0,%1,%2,%3};"
                 : "+f"(d[0]), "+f"(d[1]), "+f"(d[2]), "+f"(d[3])
                 : "r"(a[0]), "r"(a[1]), "r"(a[2]), "r"(a[3]), "r"(b[0]), "r"(b[1]));
}
__device__ __forceinline__ void cpa16(uint32_t s, const void* g) {
    asm volatile("cp.async.cg.shared.global [%0], [%1], 16;" :: "r"(s), "l"(g) : "memory");
}
__device__ __forceinline__ uint32_t packbf(float a, float b) {
    __nv_bfloat162 t = __floats2bfloat162_rn(a, b);   // a in low half
    return *(uint32_t*)&t;
}

// smem tile geometry for hgemm: 128 rows x 32 halves, padded to 40 (80B rows)
#define LDS_  40
#define TILEB (128*LDS_*2)      // 10240 B per tile

// ==================== HMMA split-bf16 GEMM: C = A@B^T (+X) ====================
// MODE 0: C = acc   MODE 1: C = acc + X   MODE 2: swiglu pairs -> Ohi/Olo bf16
template<int MODE>
__global__ void __launch_bounds__(256, 2)
hgemm(const __nv_bfloat16* __restrict__ Ahi, const __nv_bfloat16* __restrict__ Alo,
      const __nv_bfloat16* __restrict__ Bhi, const __nv_bfloat16* __restrict__ Blo,
      float* __restrict__ C, const float* __restrict__ X,
      __nv_bfloat16* __restrict__ Ohi, __nv_bfloat16* __restrict__ Olo,
      int K, int ldc) {
    extern __shared__ char smem[];
    uint32_t s0 = smem_u32(smem);

    int tid = threadIdx.x, lane = tid & 31, wid = tid >> 5;
    int m0 = blockIdx.y * 128, n0 = blockIdx.x * 128;
    int wm = wid & 1, wn = wid >> 1;     // 2 x 4 warps; warp tile 64(M) x 32(N)

    float acc[4][4][4];
    #pragma unroll
    for (int i = 0; i < 4; i++)
        #pragma unroll
        for (int j = 0; j < 4; j++)
            #pragma unroll
            for (int e = 0; e < 4; e++) acc[i][j][e] = 0.f;

    int r0l = (tid + 0)   >> 2, c0l = ((tid + 0)   & 3) * 8;
    int r1l = (tid + 256) >> 2, c1l = ((tid + 256) & 3) * 8;

    const __nv_bfloat16* gA[2] = {Ahi, Alo};
    const __nv_bfloat16* gB[2] = {Bhi, Blo};

    auto issue = [&](int buf, int kc) {
        #pragma unroll
        for (int a = 0; a < 2; a++) {
            uint32_t sa = s0 + (buf * 4 + a) * TILEB;
            cpa16(sa + (r0l * LDS_ + c0l) * 2, gA[a] + (size_t)(m0 + r0l) * K + kc + c0l);
            cpa16(sa + (r1l * LDS_ + c1l) * 2, gA[a] + (size_t)(m0 + r1l) * K + kc + c1l);
            uint32_t sb = s0 + (buf * 4 + 2 + a) * TILEB;
            cpa16(sb + (r0l * LDS_ + c0l) * 2, gB[a] + (size_t)(n0 + r0l) * K + kc + c0l);
            cpa16(sb + (r1l * LDS_ + c1l) * 2, gB[a] + (size_t)(n0 + r1l) * K + kc + c1l);
        }
        asm volatile("cp.async.commit_group;" ::: "memory");
    };

    int arow = wm * 64 + (lane & 15);
    int acol = (lane & 16) ? 8 : 0;
    int brow = wn * 32 + (lane & 7) + ((lane & 16) ? 8 : 0);
    int bcol = (lane & 8) ? 8 : 0;

    int NC = K >> 5;
    issue(0, 0);

    for (int c = 0; c < NC; ++c) {
        if (c + 1 < NC) {
            issue((c + 1) & 1, (c + 1) << 5);
            asm volatile("cp.async.wait_group 1;" ::: "memory");
        } else {
            asm volatile("cp.async.wait_group 0;" ::: "memory");
        }
        __syncthreads();

        int buf = c & 1;
        uint32_t sAh = s0 + (buf * 4 + 0) * TILEB;
        uint32_t sAl = s0 + (buf * 4 + 1) * TILEB;
        uint32_t sBh = s0 + (buf * 4 + 2) * TILEB;
        uint32_t sBl = s0 + (buf * 4 + 3) * TILEB;

        #pragma unroll
        for (int ks = 0; ks < 2; ++ks) {
            uint32_t bh[2][4], bl[2][4];
            #pragma unroll
            for (int ni2 = 0; ni2 < 2; ++ni2) {
                uint32_t off = ((brow + ni2 * 16) * LDS_ + bcol + ks * 16) * 2;
                ldsm4(bh[ni2], sBh + off);
                ldsm4(bl[ni2], sBl + off);
            }
            #pragma unroll
            for (int mi = 0; mi < 4; ++mi) {
                uint32_t aoff = ((arow + mi * 16) * LDS_ + acol + ks * 16) * 2;
                uint32_t ah[4], al[4];
                ldsm4(ah, sAh + aoff);
                ldsm4(al, sAl + aoff);
                #pragma unroll
                for (int n8 = 0; n8 < 4; ++n8) {
                    const uint32_t* bph = &bh[n8 >> 1][(n8 & 1) * 2];
                    const uint32_t* bpl = &bl[n8 >> 1][(n8 & 1) * 2];
                    mma16816(acc[mi][n8], ah, bph);
                    mma16816(acc[mi][n8], ah, bpl);
                    mma16816(acc[mi][n8], al, bph);
                }
            }
        }
        __syncthreads();
    }

    int rbase = m0 + wm * 64 + (lane >> 2);
    #pragma unroll
    for (int mi = 0; mi < 4; ++mi) {
        #pragma unroll
        for (int half = 0; half < 2; ++half) {
            int row = rbase + mi * 16 + half * 8;
            if (MODE == 2) {
                // swiglu: acc pairs (a,b) at cols (2p, 2p+1) -> g[row][p]
                int pldc = ldc >> 1;
                int pbase = (n0 >> 1) + wn * 16 + (lane & 3);
                #pragma unroll
                for (int n8 = 0; n8 < 4; ++n8) {
                    float a = acc[mi][n8][half * 2 + 0];
                    float b = acc[mi][n8][half * 2 + 1];
                    float g = a / (1.0f + expf(-a)) * b;
                    int p = pbase + n8 * 4;
                    __nv_bfloat16 hb = __float2bfloat16(g);
                    Ohi[(size_t)row * pldc + p] = hb;
                    Olo[(size_t)row * pldc + p] = __float2bfloat16(g - __bfloat162float(hb));
                }
            } else {
                int cbase = n0 + wn * 32 + (lane & 3) * 2;
                float* crow = C + (size_t)row * ldc;
                const float* xrow = (MODE == 1) ? X + (size_t)row * ldc : nullptr;
                #pragma unroll
                for (int n8 = 0; n8 < 4; ++n8) {
                    int col = cbase + n8 * 8;
                    float2 v;
                    v.x = acc[mi][n8][half * 2 + 0];
                    v.y = acc[mi][n8][half * 2 + 1];
                    if (MODE == 1) {
                        float2 xv = *(const float2*)(xrow + col);
                        v.x += xv.x; v.y += xv.y;
                    }
                    *(float2*)(crow + col) = v;
                }
            }
        }
    }
}

// ==================== unified weight prep (one launch) ====================
// W[K,N] fp32 -> transposed hi/lo bf16.  w1/w3 interleaved into w13 (rows 2n / 2n+1)
__global__ void prep_all(const float* __restrict__ wq, const float* __restrict__ wk,
                         const float* __restrict__ wv, const float* __restrict__ wo,
                         const float* __restrict__ w1, const float* __restrict__ w2,
                         const float* __restrict__ w3,
                         __nv_bfloat16* __restrict__ wqkvhi, __nv_bfloat16* __restrict__ wqkvlo,
                         __nv_bfloat16* __restrict__ wothi,  __nv_bfloat16* __restrict__ wotlo,
                         __nv_bfloat16* __restrict__ w13hi,  __nv_bfloat16* __restrict__ w13lo,
                         __nv_bfloat16* __restrict__ w2thi,  __nv_bfloat16* __restrict__ w2tlo) {
    int id = blockIdx.x;
    const float* W; __nv_bfloat16 *hi, *lo;
    int N, nb, roff = 0, ldo, inter = 0, odd = 0, local;
    if (id < 1024)      { W = wq; hi = wqkvhi; lo = wqkvlo; N = 1024; nb = 32; roff = 0;    ldo = 1024; local = id; }
    else if (id < 2048) { W = wk; hi = wqkvhi; lo = wqkvlo; N = 1024; nb = 32; roff = 1024; ldo = 1024; local = id - 1024; }
    else if (id < 3072) { W = wv; hi = wqkvhi; lo = wqkvlo; N = 1024; nb = 32; roff = 2048; ldo = 1024; local = id - 2048; }
    else if (id < 4096) { W = wo; hi = wothi;  lo = wotlo;  N = 1024; nb = 32; roff = 0;    ldo = 1024; local = id - 3072; }
    else if (id < 8192) { W = w1; hi = w13hi;  lo = w13lo;  N = 4096; nb = 128; ldo = 1024; inter = 1; odd = 0; local = id - 4096; }
    else if (id < 12288){ W = w3; hi = w13hi;  lo = w13lo;  N = 4096; nb = 128; ldo = 1024; inter = 1; odd = 1; local = id - 8192; }
    else                { W = w2; hi = w2thi;  lo = w2tlo;  N = 1024; nb = 32;  ldo = 4096; local = id - 12288; }

    __shared__ float t[32][33];
    int tx = threadIdx.x, ty = threadIdx.y;     // 32 x 8
    int n0 = (local % nb) * 32, k0 = (local / nb) * 32;
    #pragma unroll
    for (int i = 0; i < 32; i += 8)
        t[ty + i][tx] = W[(size_t)(k0 + ty + i) * N + n0 + tx];
    __syncthreads();
    #pragma unroll
    for (int i = 0; i < 32; i += 8) {
        float v = t[tx][ty + i];
        int n = n0 + ty + i;
        int row = inter ? (2 * n + odd) : (roff + n);
        size_t o = (size_t)row * ldo + k0 + tx;
        __nv_bfloat16 h = __float2bfloat16(v);
        hi[o] = h;
        lo[o] = __float2bfloat16(v - __bfloat162float(h));
    }
}

// ==================== LayerNorm + hi/lo split ====================
__global__ void ln_split(const float* __restrict__ x, const float* __restrict__ g,
                         const float* __restrict__ b, __nv_bfloat16* __restrict__ hi,
                         __nv_bfloat16* __restrict__ lo) {
    int t = blockIdx.x, tid = threadIdx.x;
    const float4* xr = (const float4*)(x + (size_t)t * D_);
    float4 xv = xr[tid];
    __shared__ float rbuf[8];
    __shared__ float s_mean, s_rstd;

    float s = xv.x + xv.y + xv.z + xv.w;
    #pragma unroll
    for (int o = 16; o; o >>= 1) s += __shfl_xor_sync(~0u, s, o);
    if ((tid & 31) == 0) rbuf[tid >> 5] = s;
    __syncthreads();
    if (tid == 0) {
        float m = 0.f;
        #pragma unroll
        for (int i = 0; i < 8; i++) m += rbuf[i];
        s_mean = m * (1.0f / D_);
    }
    __syncthreads();
    float mean = s_mean;
    float dx = xv.x - mean, dy = xv.y - mean, dz = xv.z - mean, dw = xv.w - mean;
    float s2 = dx*dx + dy*dy + dz*dz + dw*dw;
    #pragma unroll
    for (int o = 16; o; o >>= 1) s2 += __shfl_xor_sync(~0u, s2, o);
    if ((tid & 31) == 0) rbuf[tid >> 5] = s2;
    __syncthreads();
    if (tid == 0) {
        float v = 0.f;
        #pragma unroll
        for (int i = 0; i < 8; i++) v += rbuf[i];
        s_rstd = rsqrtf(v * (1.0f / D_) + 1e-6f);
    }
    __syncthreads();
    float rstd = s_rstd;
    const float4 gv = ((const float4*)g)[tid];
    const float4 bv = ((const float4*)b)[tid];
    float o0 = dx * rstd * gv.x + bv.x;
    float o1 = dy * rstd * gv.y + bv.y;
    float o2 = dz * rstd * gv.z + bv.z;
    float o3 = dw * rstd * gv.w + bv.w;
    size_t base = (size_t)t * D_ + tid * 4;
    __nv_bfloat16 h0 = __float2bfloat16(o0), h1 = __float2bfloat16(o1);
    __nv_bfloat16 h2 = __float2bfloat16(o2), h3 = __float2bfloat16(o3);
    hi[base+0]=h0; hi[base+1]=h1; hi[base+2]=h2; hi[base+3]=h3;
    lo[base+0]=__float2bfloat16(o0-__bfloat162float(h0));
    lo[base+1]=__float2bfloat16(o1-__bfloat162float(h1));
    lo[base+2]=__float2bfloat16(o2-__bfloat162float(h2));
    lo[base+3]=__float2bfloat16(o3-__bfloat162float(h3));
}

// ==================== RoPE + convert: qkv fp32 [tok,3072] -> q/k/v bf16 [b,h,s,d] ====
__global__ void rope_cvt(const float* __restrict__ qkv, __nv_bfloat16* __restrict__ qb,
                         __nv_bfloat16* __restrict__ kb, __nv_bfloat16* __restrict__ vb) {
    int t = blockIdx.x;                 // token
    int tid = threadIdx.x;              // 128
    int b = t / S_, s = t & (S_ - 1);
    int d = tid & 63;
    int dd = d & 31;
    double inv = exp(-(double)dd * (log(10000.0) / 32.0));
    double ang = (double)s * inv;
    float c = (float)cos(ang), sn = (float)sin(ang);
    const float* row = qkv + (size_t)t * QKV_LD;

    #pragma unroll
    for (int hh = 0; hh < 8; ++hh) {
        int h = hh * 2 + (tid >> 6);
        size_t oidx = ((size_t)(b * H_ + h) * S_ + s) * HD_ + d;
        // q (scaled by 1/8 = 1/sqrt(64))
        {
            float x1 = row[h * 64 + d];
            float x2 = row[h * 64 + (d ^ 32)];
            float o = (d < 32) ? (x1 * c - x2 * sn) : (x1 * c + x2 * sn);
            qb[oidx] = __float2bfloat16(o * 0.125f);
        }
        // k
        {
            float x1 = row[1024 + h * 64 + d];
            float x2 = row[1024 + h * 64 + (d ^ 32)];
            float o = (d < 32) ? (x1 * c - x2 * sn) : (x1 * c + x2 * sn);
            kb[oidx] = __float2bfloat16(o);
        }
        // v
        vb[oidx] = __float2bfloat16(row[2048 + h * 64 + d]);
    }
}

// ==================== flash attention (HMMA, sliding window 256) ====================
// grid (S/128, H, B), 256 thr. smem: Q,K,V tiles 128x64 halves, pitch 72.
#define LK_ 72
__global__ void __launch_bounds__(256, 1)
attn_mma(const __nv_bfloat16* __restrict__ qb, const __nv_bfloat16* __restrict__ kb,
         const __nv_bfloat16* __restrict__ vb,
         __nv_bfloat16* __restrict__ chi, __nv_bfloat16* __restrict__ clo) {
    extern __shared__ char smem[];
    uint32_t sQ = smem_u32(smem);
    uint32_t sK = sQ + 128 * LK_ * 2;
    uint32_t sV = sK + 128 * LK_ * 2;

    int q0 = blockIdx.x * 128;
    int h = blockIdx.y, bi = blockIdx.z;
    int tid = threadIdx.x, lane = tid & 31, w = tid >> 5;
    size_t bh = ((size_t)(bi * H_ + h)) * S_;

    // load Q tile
    for (int i = tid; i < 128 * 8; i += 256) {
        int r = i >> 3, c8 = (i & 7) * 8;
        uint4 v = *(const uint4*)(qb + (bh + q0 + r) * HD_ + c8);
        *(uint4*)(smem + (r * LK_ + c8) * 2) = v;
    }
    __syncthreads();

    // preload Q frags: 16 rows per warp
    uint32_t qf[4][4];
    {
        int ar = w * 16 + (lane & 15);
        int ac = (lane & 16) ? 8 : 0;
        #pragma unroll
        for (int kc = 0; kc < 4; ++kc)
            ldsm4(qf[kc], sQ + ((ar) * LK_ + ac + kc * 16) * 2);
    }

    float O[8][4];
    #pragma unroll
    for (int i = 0; i < 8; i++) { O[i][0]=0; O[i][1]=0; O[i][2]=0; O[i][3]=0; }
    float rm0 = -1e30f, rm1 = -1e30f, l0 = 0.f, l1 = 0.f;

    int g = lane >> 2, tq = lane & 3;
    int qrow0 = q0 + w * 16 + g;

    // tiles in order: diagonal first (always has valid entries)
    #pragma unroll
    for (int it = 0; it < 3; ++it) {
        int ord = 2 - it;
        int kbase = q0 - 256 + ord * 128;
        if (kbase + 128 <= 0) continue;

        __syncthreads();
        for (int i = tid; i < 128 * 8; i += 256) {
            int r = i >> 3, c8 = (i & 7) * 8;
            int krow = kbase + r; if (krow < 0) krow = 0;
            uint4 kv = *(const uint4*)(kb + (bh + krow) * HD_ + c8);
            uint4 vv = *(const uint4*)(vb + (bh + krow) * HD_ + c8);
            *(uint4*)(smem + (128 * LK_ + r * LK_ + c8) * 2) = kv;
            *(uint4*)(smem + (256 * LK_ + r * LK_ + c8) * 2) = vv;
        }
        __syncthreads();

        // S = Q @ K^T : 16 n8 tiles
        float sf[16][4];
        {
            int br = (lane & 7) + ((lane & 16) ? 8 : 0);
            int bc = (lane & 8) ? 8 : 0;
            #pragma unroll
            for (int ni2 = 0; ni2 < 8; ++ni2) {
                float s4[8] = {0,0,0,0,0,0,0,0};
                #pragma unroll
                for (int kc = 0; kc < 4; ++kc) {
                    uint32_t kf[4];
                    ldsm4(kf, sK + ((ni2 * 16 + br) * LK_ + bc + kc * 16) * 2);
                    mma16816(s4,     qf[kc], kf + 0);
                    mma16816(s4 + 4, qf[kc], kf + 2);
                }
                #pragma unroll
                for (int e = 0; e < 4; e++) { sf[2*ni2][e] = s4[e]; sf[2*ni2+1][e] = s4[4+e]; }
            }
        }

        // mask + tile max
        float tm0 = -1e30f, tm1 = -1e30f;
        #pragma unroll
        for (int ni = 0; ni < 16; ++ni) {
            int colb = kbase + ni * 8 + tq * 2;
            #pragma unroll
            for (int e = 0; e < 2; ++e) {
                int col = colb + e;
                int r0 = qrow0 - col, r1 = qrow0 + 8 - col;
                if (!(col >= 0 && r0 >= 0 && r0 < W_)) sf[ni][e]     = -1e30f;
                if (!(col >= 0 && r1 >= 0 && r1 < W_)) sf[ni][2 + e] = -1e30f;
                tm0 = fmaxf(tm0, sf[ni][e]);
                tm1 = fmaxf(tm1, sf[ni][2 + e]);
            }
        }
        tm0 = fmaxf(tm0, __shfl_xor_sync(~0u, tm0, 1));
        tm0 = fmaxf(tm0, __shfl_xor_sync(~0u, tm0, 2));
        tm1 = fmaxf(tm1, __shfl_xor_sync(~0u, tm1, 1));
        tm1 = fmaxf(tm1, __shfl_xor_sync(~0u, tm1, 2));

        float m0 = fmaxf(rm0, tm0), m1 = fmaxf(rm1, tm1);
        float a0 = __expf(rm0 - m0), a1 = __expf(rm1 - m1);
        rm0 = m0; rm1 = m1;
        #pragma unroll
        for (int nd = 0; nd < 8; ++nd) {
            O[nd][0] *= a0; O[nd][1] *= a0; O[nd][2] *= a1; O[nd][3] *= a1;
        }
        float rs0 = 0.f, rs1 = 0.f;
        #pragma unroll
        for (int ni = 0; ni < 16; ++ni) {
            float p0 = __expf(sf[ni][0] - m0);
            float p1 = __expf(sf[ni][1] - m0);
            float p2 = __expf(sf[ni][2] - m1);
            float p3 = __expf(sf[ni][3] - m1);
            sf[ni][0] = p0; sf[ni][1] = p1; sf[ni][2] = p2; sf[ni][3] = p3;
            rs0 += p0 + p1; rs1 += p2 + p3;
        }
        rs0 += __shfl_xor_sync(~0u, rs0, 1); rs0 += __shfl_xor_sync(~0u, rs0, 2);
        rs1 += __shfl_xor_sync(~0u, rs1, 1); rs1 += __shfl_xor_sync(~0u, rs1, 2);
        l0 = l0 * a0 + rs0;
        l1 = l1 * a1 + rs1;

        // O += P @ V
        #pragma unroll
        for (int j = 0; j < 8; ++j) {
            uint32_t aP[4];
            aP[0] = packbf(sf[2*j][0],   sf[2*j][1]);
            aP[1] = packbf(sf[2*j][2],   sf[2*j][3]);
            aP[2] = packbf(sf[2*j+1][0], sf[2*j+1][1]);
            aP[3] = packbf(sf[2*j+1][2], sf[2*j+1][3]);
            int sel = lane >> 3;
            int vr = 16 * j + (lane & 7) + ((sel & 1) * 8);
            #pragma unroll
            for (int np = 0; np < 4; ++np) {
                uint32_t vf[4];
                ldsm4t(vf, sV + (vr * LK_ + np * 16 + ((sel >> 1) * 8)) * 2);
                mma16816(O[2*np],     aP, vf + 0);
                mma16816(O[2*np + 1], aP, vf + 2);
            }
        }
    }

    // write ctx hi/lo: [tok, 1024] at head h
    float i0 = 1.0f / l0, i1 = 1.0f / l1;
    size_t r0o = ((size_t)(bi * S_ + qrow0)) * D_ + h * HD_;
    size_t r1o = ((size_t)(bi * S_ + qrow0 + 8)) * D_ + h * HD_;
    #pragma unroll
    for (int nd = 0; nd < 8; ++nd) {
        int col = nd * 8 + tq * 2;
        #pragma unroll
        for (int e = 0; e < 2; ++e) {
            float v0 = O[nd][e] * i0;
            float v1 = O[nd][2 + e] * i1;
            __nv_bfloat16 h0 = __float2bfloat16(v0);
            __nv_bfloat16 h1 = __float2bfloat16(v1);
            chi[r0o + col + e] = h0;
            clo[r0o + col + e] = __float2bfloat16(v0 - __bfloat162float(h0));
            chi[r1o + col + e] = h1;
            clo[r1o + col + e] = __float2bfloat16(v1 - __bfloat162float(h1));
        }
    }
}

// ==================== launch ====================
extern "C" void kernel_launch(void* const* d_in, const int* in_sizes, int n_in,
                              void* d_out, int out_size) {
    const float* hidden = (const float*)d_in[0];
    const float* wq = (const float*)d_in[1];
    const float* wk = (const float*)d_in[2];
    const float* wv = (const float*)d_in[3];
    const float* wo = (const float*)d_in[4];
    const float* w1 = (const float*)d_in[5];
    const float* w2 = (const float*)d_in[6];
    const float* w3 = (const float*)d_in[7];
    const float* ln1_g = (const float*)d_in[8];
    const float* ln1_b = (const float*)d_in[9];
    const float* ln2_g = (const float*)d_in[10];
    const float* ln2_b = (const float*)d_in[11];
    float* out = (float*)d_out;

    float *qkv, *hid;
    __nv_bfloat16 *xahi, *xalo, *cahi, *calo, *ghi, *glo, *qb, *kb, *vb;
    __nv_bfloat16 *wqkvhi, *wqkvlo, *wothi, *wotlo, *w13hi, *w13lo, *w2thi, *w2tlo;
    cudaGetSymbolAddress((void**)&qkv, g_qkv);
    cudaGetSymbolAddress((void**)&hid, g_hid);
    cudaGetSymbolAddress((void**)&xahi, g_xahi);
    cudaGetSymbolAddress((void**)&xalo, g_xalo);
    cudaGetSymbolAddress((void**)&cahi, g_cahi);
    cudaGetSymbolAddress((void**)&calo, g_calo);
    cudaGetSymbolAddress((void**)&ghi, g_ghi);
    cudaGetSymbolAddress((void**)&glo, g_glo);
    cudaGetSymbolAddress((void**)&qb, g_qb);
    cudaGetSymbolAddress((void**)&kb, g_kb);
    cudaGetSymbolAddress((void**)&vb, g_vb);
    cudaGetSymbolAddress((void**)&wqkvhi, g_wqkvhi);
    cudaGetSymbolAddress((void**)&wqkvlo, g_wqkvlo);
    cudaGetSymbolAddress((void**)&wothi, g_wothi);
    cudaGetSymbolAddress((void**)&wotlo, g_wotlo);
    cudaGetSymbolAddress((void**)&w13hi, g_w13hi);
    cudaGetSymbolAddress((void**)&w13lo, g_w13lo);
    cudaGetSymbolAddress((void**)&w2thi, g_w2thi);
    cudaGetSymbolAddress((void**)&w2tlo, g_w2tlo);

    const int SMEM_DYN = 8 * TILEB;     // 81920 B
    cudaFuncSetAttribute(hgemm<0>, cudaFuncAttributeMaxDynamicSharedMemorySize, SMEM_DYN);
    cudaFuncSetAttribute(hgemm<1>, cudaFuncAttributeMaxDynamicSharedMemorySize, SMEM_DYN);
    cudaFuncSetAttribute(hgemm<2>, cudaFuncAttributeMaxDynamicSharedMemorySize, SMEM_DYN);
    const int SMEM_ATT = 3 * 128 * LK_ * 2;   // 55296 B
    cudaFuncSetAttribute(attn_mma, cudaFuncAttributeMaxDynamicSharedMemorySize, SMEM_ATT);

    // 0: weight prep (single launch)
    prep_all<<<16384, dim3(32, 8)>>>(wq, wk, wv, wo, w1, w2, w3,
                                     wqkvhi, wqkvlo, wothi, wotlo,
                                     w13hi, w13lo, w2thi, w2tlo);
    // 1: LN1
    ln_split<<<TOK, 256>>>(hidden, ln1_g, ln1_b, xahi, xalo);
    // 2: QKV GEMM
    hgemm<0><<<dim3(24, 32), 256, SMEM_DYN>>>(xahi, xalo, wqkvhi, wqkvlo,
                                              qkv, nullptr, ghi, glo, 1024, QKV_LD);
    // 3: RoPE + bf16 convert
    rope_cvt<<<TOK, 128>>>(qkv, qb, kb, vb);
    // 4: flash attention
    attn_mma<<<dim3(S_ / 128, H_, B_), 256, SMEM_ATT>>>(qb, kb, vb, cahi, calo);
    // 5: WO GEMM (+ residual)
    hgemm<1><<<dim3(8, 32), 256, SMEM_DYN>>>(cahi, calo, wothi, wotlo,
                                             hid, hidden, ghi, glo, 1024, D_);
    // 6: LN2
    ln_split<<<TOK, 256>>>(hid, ln2_g, ln2_b, xahi, xalo);
    // 7: W13 GEMM with fused swiglu -> g hi/lo
    hgemm<2><<<dim3(64, 32), 256, SMEM_DYN>>>(xahi, xalo, w13hi, w13lo,
                                              nullptr, nullptr, ghi, glo, 1024, 8192);
    // 8: W2 GEMM (+ residual)
    hgemm<1><<<dim3(8, 32), 256, SMEM_DYN>>>(ghi, glo, w2thi, w2tlo,
                                             out, hid, ghi, glo, 4096, D_);
}

// round 6
// speedup vs baseline: 13.9373x; 2.5036x over previous
#include <cuda_runtime.h>
#include <cuda_fp16.h>
#include <math.h>
#include <stdint.h>

#define B_  2
#define S_  2048
#define D_  1024
#define H_  16
#define HD_ 64
#define I_  4096
#define W_  256
#define TOK (B_*S_)
#define QKV_LD 3072

// ==================== scratch (__device__ globals; no allocs) ====================
__device__ float g_qkv[(size_t)TOK*QKV_LD];
__device__ float g_hid[TOK*D_];
__device__ float2 g_tab[S_*32];

__device__ __half g_xa[TOK*D_];
__device__ __half g_ca[TOK*D_];
__device__ __half g_g [(size_t)TOK*I_];
__device__ __half g_qh[TOK*D_];   // [b,h,s,d] scaled by 0.125
__device__ __half g_kh[TOK*D_];
__device__ __half g_vh[TOK*D_];

// transposed weights: [N_rows, K] fp16 (w13: rows interleaved w1/w3)
__device__ __half g_wqkv[3072*1024];
__device__ __half g_wot [1024*1024];
__device__ __half g_w13 [(size_t)8192*1024];
__device__ __half g_w2t [(size_t)1024*4096];

// ==================== helpers ====================
__device__ __forceinline__ uint32_t smem_u32(const void* p) {
    return (uint32_t)__cvta_generic_to_shared(p);
}
__device__ __forceinline__ void ldsm4(uint32_t* r, uint32_t a) {
    asm volatile("ldmatrix.sync.aligned.m8n8.x4.shared.b16 {%0,%1,%2,%3}, [%4];"
                 : "=r"(r[0]), "=r"(r[1]), "=r"(r[2]), "=r"(r[3]) : "r"(a));
}
__device__ __forceinline__ void ldsm4t(uint32_t* r, uint32_t a) {
    asm volatile("ldmatrix.sync.aligned.m8n8.x4.trans.shared.b16 {%0,%1,%2,%3}, [%4];"
                 : "=r"(r[0]), "=r"(r[1]), "=r"(r[2]), "=r"(r[3]) : "r"(a));
}
__device__ __forceinline__ void mma16816h(float* d, const uint32_t* a, const uint32_t* b) {
    asm volatile("mma.sync.aligned.m16n8k16.row.col.f32.f16.f16.f32 "
                 "{%0,%1,%2,%3}, {%4,%5,%6,%7}, {%8,%9}, {%0,%1,%2,%3};"
                 : "+f"(d[0]), "+f"(d[1]), "+f"(d[2]), "+f"(d[3])
                 : "r"(a[0]), "r"(a[1]), "r"(a[2]), "r"(a[3]), "r"(b[0]), "r"(b[1]));
}
__device__ __forceinline__ void cpa16(uint32_t s, const void* g) {
    asm volatile("cp.async.cg.shared.global [%0], [%1], 16;" :: "r"(s), "l"(g) : "memory");
}
__device__ __forceinline__ uint32_t packh(float a, float b) {
    __half2 t = __floats2half2_rn(a, b);   // a in low half
    return *(uint32_t*)&t;
}

// smem tile geometry for hgemm: 128 rows x 64 halves, pitch 72 halves (144B)
#define LK2 72
#define TILE2B (128*LK2*2)      // 18432 B per tile

// ==================== HMMA fp16 GEMM: C = A@B^T (+X) ====================
// MODE 0: C = acc   MODE 1: C = acc + X   MODE 2: swiglu pairs -> O fp16
template<int MODE>
__global__ void __launch_bounds__(256, 2)
hgemm(const __half* __restrict__ A, const __half* __restrict__ B,
      float* __restrict__ C, const float* __restrict__ X,
      __half* __restrict__ O, int K, int ldc) {
    extern __shared__ char smem[];
    uint32_t s0 = smem_u32(smem);

    int tid = threadIdx.x, lane = tid & 31, wid = tid >> 5;
    int m0 = blockIdx.y * 128, n0 = blockIdx.x * 128;
    int wm = wid & 1, wn = wid >> 1;     // 2 x 4 warps; warp tile 64(M) x 32(N)

    float acc[4][4][4];
    #pragma unroll
    for (int i = 0; i < 4; i++)
        #pragma unroll
        for (int j = 0; j < 4; j++)
            #pragma unroll
            for (int e = 0; e < 4; e++) acc[i][j][e] = 0.f;

    auto issue = [&](int buf, int kc) {
        uint32_t sa = s0 + buf * 2 * TILE2B;
        uint32_t sb = sa + TILE2B;
        #pragma unroll
        for (int t = 0; t < 4; ++t) {
            int idx = tid + t * 256;            // 1024 chunks per tile
            int r = idx >> 3, c = (idx & 7) * 8;
            cpa16(sa + (r * LK2 + c) * 2, A + (size_t)(m0 + r) * K + kc + c);
            cpa16(sb + (r * LK2 + c) * 2, B + (size_t)(n0 + r) * K + kc + c);
        }
        asm volatile("cp.async.commit_group;" ::: "memory");
    };

    int arow = wm * 64 + (lane & 15);
    int acol = (lane & 16) ? 8 : 0;
    int brow = wn * 32 + (lane & 7) + ((lane & 16) ? 8 : 0);
    int bcol = (lane & 8) ? 8 : 0;

    int NC = K >> 6;
    issue(0, 0);

    for (int c = 0; c < NC; ++c) {
        if (c + 1 < NC) {
            issue((c + 1) & 1, (c + 1) << 6);
            asm volatile("cp.async.wait_group 1;" ::: "memory");
        } else {
            asm volatile("cp.async.wait_group 0;" ::: "memory");
        }
        __syncthreads();

        uint32_t sA = s0 + (c & 1) * 2 * TILE2B;
        uint32_t sB = sA + TILE2B;

        #pragma unroll
        for (int ks = 0; ks < 4; ++ks) {
            uint32_t bf[2][4];
            #pragma unroll
            for (int ni2 = 0; ni2 < 2; ++ni2)
                ldsm4(bf[ni2], sB + ((brow + ni2 * 16) * LK2 + bcol + ks * 16) * 2);
            #pragma unroll
            for (int mi = 0; mi < 4; ++mi) {
                uint32_t af[4];
                ldsm4(af, sA + ((arow + mi * 16) * LK2 + acol + ks * 16) * 2);
                #pragma unroll
                for (int n8 = 0; n8 < 4; ++n8)
                    mma16816h(acc[mi][n8], af, &bf[n8 >> 1][(n8 & 1) * 2]);
            }
        }
        __syncthreads();
    }

    int rbase = m0 + wm * 64 + (lane >> 2);
    #pragma unroll
    for (int mi = 0; mi < 4; ++mi) {
        #pragma unroll
        for (int half = 0; half < 2; ++half) {
            int row = rbase + mi * 16 + half * 8;
            if (MODE == 2) {
                // swiglu: acc pairs (a,b) at cols (2p, 2p+1) -> g[row][p]
                int pldc = ldc >> 1;
                int pbase = (n0 >> 1) + wn * 16 + (lane & 3);
                #pragma unroll
                for (int n8 = 0; n8 < 4; ++n8) {
                    float a = acc[mi][n8][half * 2 + 0];
                    float b = acc[mi][n8][half * 2 + 1];
                    float g = a / (1.0f + expf(-a)) * b;
                    O[(size_t)row * pldc + pbase + n8 * 4] = __float2half(g);
                }
            } else {
                int cbase = n0 + wn * 32 + (lane & 3) * 2;
                float* crow = C + (size_t)row * ldc;
                const float* xrow = (MODE == 1) ? X + (size_t)row * ldc : nullptr;
                #pragma unroll
                for (int n8 = 0; n8 < 4; ++n8) {
                    int col = cbase + n8 * 8;
                    float2 v;
                    v.x = acc[mi][n8][half * 2 + 0];
                    v.y = acc[mi][n8][half * 2 + 1];
                    if (MODE == 1) {
                        float2 xv = *(const float2*)(xrow + col);
                        v.x += xv.x; v.y += xv.y;
                    }
                    *(float2*)(crow + col) = v;
                }
            }
        }
    }
}

// ==================== unified weight prep (one launch) ====================
__global__ void prep_all(const float* __restrict__ wq, const float* __restrict__ wk,
                         const float* __restrict__ wv, const float* __restrict__ wo,
                         const float* __restrict__ w1, const float* __restrict__ w2,
                         const float* __restrict__ w3,
                         __half* __restrict__ wqkv, __half* __restrict__ wot,
                         __half* __restrict__ w13,  __half* __restrict__ w2t) {
    int id = blockIdx.x;
    const float* W; __half* dst;
    int N, nb, roff = 0, ldo, inter = 0, odd = 0, local;
    if (id < 1024)      { W = wq; dst = wqkv; N = 1024; nb = 32; roff = 0;    ldo = 1024; local = id; }
    else if (id < 2048) { W = wk; dst = wqkv; N = 1024; nb = 32; roff = 1024; ldo = 1024; local = id - 1024; }
    else if (id < 3072) { W = wv; dst = wqkv; N = 1024; nb = 32; roff = 2048; ldo = 1024; local = id - 2048; }
    else if (id < 4096) { W = wo; dst = wot;  N = 1024; nb = 32; roff = 0;    ldo = 1024; local = id - 3072; }
    else if (id < 8192) { W = w1; dst = w13;  N = 4096; nb = 128; ldo = 1024; inter = 1; odd = 0; local = id - 4096; }
    else if (id < 12288){ W = w3; dst = w13;  N = 4096; nb = 128; ldo = 1024; inter = 1; odd = 1; local = id - 8192; }
    else                { W = w2; dst = w2t;  N = 1024; nb = 32;  ldo = 4096; local = id - 12288; }

    __shared__ float t[32][33];
    int tx = threadIdx.x, ty = threadIdx.y;     // 32 x 8
    int n0 = (local % nb) * 32, k0 = (local / nb) * 32;
    #pragma unroll
    for (int i = 0; i < 32; i += 8)
        t[ty + i][tx] = W[(size_t)(k0 + ty + i) * N + n0 + tx];
    __syncthreads();
    #pragma unroll
    for (int i = 0; i < 32; i += 8) {
        float v = t[tx][ty + i];
        int n = n0 + ty + i;
        int row = inter ? (2 * n + odd) : (roff + n);
        dst[(size_t)row * ldo + k0 + tx] = __float2half(v);
    }
}

// ==================== LayerNorm -> fp16 ====================
__global__ void ln_h(const float* __restrict__ x, const float* __restrict__ g,
                     const float* __restrict__ b, __half* __restrict__ y) {
    int t = blockIdx.x, tid = threadIdx.x;
    const float4* xr = (const float4*)(x + (size_t)t * D_);
    float4 xv = xr[tid];
    __shared__ float rbuf[8];
    __shared__ float s_mean, s_rstd;

    float s = xv.x + xv.y + xv.z + xv.w;
    #pragma unroll
    for (int o = 16; o; o >>= 1) s += __shfl_xor_sync(~0u, s, o);
    if ((tid & 31) == 0) rbuf[tid >> 5] = s;
    __syncthreads();
    if (tid == 0) {
        float m = 0.f;
        #pragma unroll
        for (int i = 0; i < 8; i++) m += rbuf[i];
        s_mean = m * (1.0f / D_);
    }
    __syncthreads();
    float mean = s_mean;
    float dx = xv.x - mean, dy = xv.y - mean, dz = xv.z - mean, dw = xv.w - mean;
    float s2 = dx*dx + dy*dy + dz*dz + dw*dw;
    #pragma unroll
    for (int o = 16; o; o >>= 1) s2 += __shfl_xor_sync(~0u, s2, o);
    if ((tid & 31) == 0) rbuf[tid >> 5] = s2;
    __syncthreads();
    if (tid == 0) {
        float v = 0.f;
        #pragma unroll
        for (int i = 0; i < 8; i++) v += rbuf[i];
        s_rstd = rsqrtf(v * (1.0f / D_) + 1e-6f);
    }
    __syncthreads();
    float rstd = s_rstd;
    const float4 gv = ((const float4*)g)[tid];
    const float4 bv = ((const float4*)b)[tid];
    size_t base = (size_t)t * D_ + tid * 4;
    y[base+0] = __float2half(dx * rstd * gv.x + bv.x);
    y[base+1] = __float2half(dy * rstd * gv.y + bv.y);
    y[base+2] = __float2half(dz * rstd * gv.z + bv.z);
    y[base+3] = __float2half(dw * rstd * gv.w + bv.w);
}

// ==================== RoPE table (double math, once) ====================
__global__ void build_tab(float2* __restrict__ tab) {
    int i = blockIdx.x * 256 + threadIdx.x;     // S*32
    int s = i >> 5, dd = i & 31;
    double inv = exp(-(double)dd * (log(10000.0) / 32.0));
    double ang = (double)s * inv;
    tab[i] = make_float2((float)cos(ang), (float)sin(ang));
}

// ==================== RoPE + convert: qkv fp32 -> q/k/v fp16 [b,h,s,d] ====================
__global__ void rope_cvt(const float* __restrict__ qkv, const float2* __restrict__ tab,
                         __half* __restrict__ qh, __half* __restrict__ kh,
                         __half* __restrict__ vh) {
    int t = blockIdx.x;                 // token
    int tid = threadIdx.x;              // 128
    int b = t / S_, s = t & (S_ - 1);
    int d = tid & 63;
    float2 cs = tab[s * 32 + (d & 31)];
    float c = cs.x, sn = cs.y;
    const float* row = qkv + (size_t)t * QKV_LD;

    #pragma unroll
    for (int hh = 0; hh < 8; ++hh) {
        int h = hh * 2 + (tid >> 6);
        size_t oidx = ((size_t)(b * H_ + h) * S_ + s) * HD_ + d;
        {
            float x1 = row[h * 64 + d];
            float x2 = row[h * 64 + (d ^ 32)];
            float o = (d < 32) ? (x1 * c - x2 * sn) : (x1 * c + x2 * sn);
            qh[oidx] = __float2half(o * 0.125f);
        }
        {
            float x1 = row[1024 + h * 64 + d];
            float x2 = row[1024 + h * 64 + (d ^ 32)];
            float o = (d < 32) ? (x1 * c - x2 * sn) : (x1 * c + x2 * sn);
            kh[oidx] = __float2half(o);
        }
        vh[oidx] = __float2half(row[2048 + h * 64 + d]);
    }
}

// ==================== flash attention (HMMA fp16, sliding window 256) ====================
#define LK_ 72
__global__ void __launch_bounds__(256, 1)
attn_mma(const __half* __restrict__ qh, const __half* __restrict__ kh,
         const __half* __restrict__ vh, __half* __restrict__ ch) {
    extern __shared__ char smem[];
    uint32_t sQ = smem_u32(smem);
    uint32_t sK = sQ + 128 * LK_ * 2;
    uint32_t sV = sK + 128 * LK_ * 2;

    int q0 = blockIdx.x * 128;
    int h = blockIdx.y, bi = blockIdx.z;
    int tid = threadIdx.x, lane = tid & 31, w = tid >> 5;
    size_t bh = ((size_t)(bi * H_ + h)) * S_;

    for (int i = tid; i < 128 * 8; i += 256) {
        int r = i >> 3, c8 = (i & 7) * 8;
        uint4 v = *(const uint4*)(qh + (bh + q0 + r) * HD_ + c8);
        *(uint4*)(smem + (r * LK_ + c8) * 2) = v;
    }
    __syncthreads();

    uint32_t qf[4][4];
    {
        int ar = w * 16 + (lane & 15);
        int ac = (lane & 16) ? 8 : 0;
        #pragma unroll
        for (int kc = 0; kc < 4; ++kc)
            ldsm4(qf[kc], sQ + (ar * LK_ + ac + kc * 16) * 2);
    }

    float O[8][4];
    #pragma unroll
    for (int i = 0; i < 8; i++) { O[i][0]=0; O[i][1]=0; O[i][2]=0; O[i][3]=0; }
    float rm0 = -1e30f, rm1 = -1e30f, l0 = 0.f, l1 = 0.f;

    int g = lane >> 2, tq = lane & 3;
    int qrow0 = q0 + w * 16 + g;

    #pragma unroll
    for (int it = 0; it < 3; ++it) {
        int ord = 2 - it;                    // diagonal tile first
        int kbase = q0 - 256 + ord * 128;
        if (kbase + 128 <= 0) continue;

        __syncthreads();
        for (int i = tid; i < 128 * 8; i += 256) {
            int r = i >> 3, c8 = (i & 7) * 8;
            int krow = kbase + r; if (krow < 0) krow = 0;
            uint4 kv = *(const uint4*)(kh + (bh + krow) * HD_ + c8);
            uint4 vv = *(const uint4*)(vh + (bh + krow) * HD_ + c8);
            *(uint4*)(smem + (128 * LK_ + r * LK_ + c8) * 2) = kv;
            *(uint4*)(smem + (256 * LK_ + r * LK_ + c8) * 2) = vv;
        }
        __syncthreads();

        float sf[16][4];
        {
            int br = (lane & 7) + ((lane & 16) ? 8 : 0);
            int bc = (lane & 8) ? 8 : 0;
            #pragma unroll
            for (int ni2 = 0; ni2 < 8; ++ni2) {
                float s4[8] = {0,0,0,0,0,0,0,0};
                #pragma unroll
                for (int kc = 0; kc < 4; ++kc) {
                    uint32_t kf[4];
                    ldsm4(kf, sK + ((ni2 * 16 + br) * LK_ + bc + kc * 16) * 2);
                    mma16816h(s4,     qf[kc], kf + 0);
                    mma16816h(s4 + 4, qf[kc], kf + 2);
                }
                #pragma unroll
                for (int e = 0; e < 4; e++) { sf[2*ni2][e] = s4[e]; sf[2*ni2+1][e] = s4[4+e]; }
            }
        }

        float tm0 = -1e30f, tm1 = -1e30f;
        #pragma unroll
        for (int ni = 0; ni < 16; ++ni) {
            int colb = kbase + ni * 8 + tq * 2;
            #pragma unroll
            for (int e = 0; e < 2; ++e) {
                int col = colb + e;
                int r0 = qrow0 - col, r1 = qrow0 + 8 - col;
                if (!(col >= 0 && r0 >= 0 && r0 < W_)) sf[ni][e]     = -1e30f;
                if (!(col >= 0 && r1 >= 0 && r1 < W_)) sf[ni][2 + e] = -1e30f;
                tm0 = fmaxf(tm0, sf[ni][e]);
                tm1 = fmaxf(tm1, sf[ni][2 + e]);
            }
        }
        tm0 = fmaxf(tm0, __shfl_xor_sync(~0u, tm0, 1));
        tm0 = fmaxf(tm0, __shfl_xor_sync(~0u, tm0, 2));
        tm1 = fmaxf(tm1, __shfl_xor_sync(~0u, tm1, 1));
        tm1 = fmaxf(tm1, __shfl_xor_sync(~0u, tm1, 2));

        float m0 = fmaxf(rm0, tm0), m1 = fmaxf(rm1, tm1);
        float a0 = __expf(rm0 - m0), a1 = __expf(rm1 - m1);
        rm0 = m0; rm1 = m1;
        #pragma unroll
        for (int nd = 0; nd < 8; ++nd) {
            O[nd][0] *= a0; O[nd][1] *= a0; O[nd][2] *= a1; O[nd][3] *= a1;
        }
        float rs0 = 0.f, rs1 = 0.f;
        #pragma unroll
        for (int ni = 0; ni < 16; ++ni) {
            float p0 = __expf(sf[ni][0] - m0);
            float p1 = __expf(sf[ni][1] - m0);
            float p2 = __expf(sf[ni][2] - m1);
            float p3 = __expf(sf[ni][3] - m1);
            sf[ni][0] = p0; sf[ni][1] = p1; sf[ni][2] = p2; sf[ni][3] = p3;
            rs0 += p0 + p1; rs1 += p2 + p3;
        }
        rs0 += __shfl_xor_sync(~0u, rs0, 1); rs0 += __shfl_xor_sync(~0u, rs0, 2);
        rs1 += __shfl_xor_sync(~0u, rs1, 1); rs1 += __shfl_xor_sync(~0u, rs1, 2);
        l0 = l0 * a0 + rs0;
        l1 = l1 * a1 + rs1;

        #pragma unroll
        for (int j = 0; j < 8; ++j) {
            uint32_t aP[4];
            aP[0] = packh(sf[2*j][0],   sf[2*j][1]);
            aP[1] = packh(sf[2*j][2],   sf[2*j][3]);
            aP[2] = packh(sf[2*j+1][0], sf[2*j+1][1]);
            aP[3] = packh(sf[2*j+1][2], sf[2*j+1][3]);
            int sel = lane >> 3;
            int vr = 16 * j + (lane & 7) + ((sel & 1) * 8);
            #pragma unroll
            for (int np = 0; np < 4; ++np) {
                uint32_t vf[4];
                ldsm4t(vf, sV + (vr * LK_ + np * 16 + ((sel >> 1) * 8)) * 2);
                mma16816h(O[2*np],     aP, vf + 0);
                mma16816h(O[2*np + 1], aP, vf + 2);
            }
        }
    }

    float i0 = 1.0f / l0, i1 = 1.0f / l1;
    size_t r0o = ((size_t)(bi * S_ + qrow0)) * D_ + h * HD_;
    size_t r1o = ((size_t)(bi * S_ + qrow0 + 8)) * D_ + h * HD_;
    #pragma unroll
    for (int nd = 0; nd < 8; ++nd) {
        int col = nd * 8 + tq * 2;
        #pragma unroll
        for (int e = 0; e < 2; ++e) {
            ch[r0o + col + e] = __float2half(O[nd][e] * i0);
            ch[r1o + col + e] = __float2half(O[nd][2 + e] * i1);
        }
    }
}

// ==================== launch ====================
extern "C" void kernel_launch(void* const* d_in, const int* in_sizes, int n_in,
                              void* d_out, int out_size) {
    const float* hidden = (const float*)d_in[0];
    const float* wq = (const float*)d_in[1];
    const float* wk = (const float*)d_in[2];
    const float* wv = (const float*)d_in[3];
    const float* wo = (const float*)d_in[4];
    const float* w1 = (const float*)d_in[5];
    const float* w2 = (const float*)d_in[6];
    const float* w3 = (const float*)d_in[7];
    const float* ln1_g = (const float*)d_in[8];
    const float* ln1_b = (const float*)d_in[9];
    const float* ln2_g = (const float*)d_in[10];
    const float* ln2_b = (const float*)d_in[11];
    float* out = (float*)d_out;

    float *qkv, *hid; float2* tab;
    __half *xa, *ca, *gg, *qh, *kh, *vh, *wqkv, *wot, *w13, *w2t;
    cudaGetSymbolAddress((void**)&qkv, g_qkv);
    cudaGetSymbolAddress((void**)&hid, g_hid);
    cudaGetSymbolAddress((void**)&tab, g_tab);
    cudaGetSymbolAddress((void**)&xa, g_xa);
    cudaGetSymbolAddress((void**)&ca, g_ca);
    cudaGetSymbolAddress((void**)&gg, g_g);
    cudaGetSymbolAddress((void**)&qh, g_qh);
    cudaGetSymbolAddress((void**)&kh, g_kh);
    cudaGetSymbolAddress((void**)&vh, g_vh);
    cudaGetSymbolAddress((void**)&wqkv, g_wqkv);
    cudaGetSymbolAddress((void**)&wot, g_wot);
    cudaGetSymbolAddress((void**)&w13, g_w13);
    cudaGetSymbolAddress((void**)&w2t, g_w2t);

    const int SMEM_G = 4 * TILE2B;      // 73728 B (2 stages x A,B)
    cudaFuncSetAttribute(hgemm<0>, cudaFuncAttributeMaxDynamicSharedMemorySize, SMEM_G);
    cudaFuncSetAttribute(hgemm<1>, cudaFuncAttributeMaxDynamicSharedMemorySize, SMEM_G);
    cudaFuncSetAttribute(hgemm<2>, cudaFuncAttributeMaxDynamicSharedMemorySize, SMEM_G);
    const int SMEM_ATT = 3 * 128 * LK_ * 2;   // 55296 B
    cudaFuncSetAttribute(attn_mma, cudaFuncAttributeMaxDynamicSharedMemorySize, SMEM_ATT);

    build_tab<<<(S_ * 32) / 256, 256>>>(tab);
    prep_all<<<16384, dim3(32, 8)>>>(wq, wk, wv, wo, w1, w2, w3, wqkv, wot, w13, w2t);

    // --- attention sub-block ---
    ln_h<<<TOK, 256>>>(hidden, ln1_g, ln1_b, xa);
    hgemm<0><<<dim3(24, 32), 256, SMEM_G>>>(xa, wqkv, qkv, nullptr, nullptr, 1024, QKV_LD);
    rope_cvt<<<TOK, 128>>>(qkv, tab, qh, kh, vh);
    attn_mma<<<dim3(S_ / 128, H_, B_), 256, SMEM_ATT>>>(qh, kh, vh, ca);
    hgemm<1><<<dim3(8, 32), 256, SMEM_G>>>(ca, wot, hid, hidden, nullptr, 1024, D_);

    // --- SwiGLU MLP sub-block ---
    ln_h<<<TOK, 256>>>(hid, ln2_g, ln2_b, xa);
    hgemm<2><<<dim3(64, 32), 256, SMEM_G>>>(xa, w13, nullptr, nullptr, gg, 1024, 8192);
    hgemm<1><<<dim3(8, 32), 256, SMEM_G>>>(gg, w2t, out, hid, nullptr, 4096, D_);
}

// round 7
// speedup vs baseline: 14.7090x; 1.0554x over previous
#include <cuda_runtime.h>
#include <cuda_fp16.h>
#include <math.h>
#include <stdint.h>

#define B_  2
#define S_  2048
#define D_  1024
#define H_  16
#define HD_ 64
#define I_  4096
#define W_  256
#define TOK (B_*S_)
#define QKV_LD 3072

// ==================== scratch (__device__ globals; no allocs) ====================
__device__ float g_hid[TOK*D_];
__device__ float2 g_tab[S_*32];

__device__ __half g_qkvh[(size_t)TOK*QKV_LD];
__device__ __half g_xa[TOK*D_];
__device__ __half g_ca[TOK*D_];
__device__ __half g_g [(size_t)TOK*I_];
__device__ __half g_qh[TOK*D_];   // [b,h,s,d] scaled by 0.125
__device__ __half g_kh[TOK*D_];
__device__ __half g_vh[TOK*D_];

// transposed weights: [N_rows, K] fp16 (w13: rows interleaved w1/w3)
__device__ __half g_wqkv[3072*1024];
__device__ __half g_wot [1024*1024];
__device__ __half g_w13 [(size_t)8192*1024];
__device__ __half g_w2t [(size_t)1024*4096];

// ==================== helpers ====================
__device__ __forceinline__ uint32_t smem_u32(const void* p) {
    return (uint32_t)__cvta_generic_to_shared(p);
}
__device__ __forceinline__ void ldsm4(uint32_t* r, uint32_t a) {
    asm volatile("ldmatrix.sync.aligned.m8n8.x4.shared.b16 {%0,%1,%2,%3}, [%4];"
                 : "=r"(r[0]), "=r"(r[1]), "=r"(r[2]), "=r"(r[3]) : "r"(a));
}
__device__ __forceinline__ void ldsm4t(uint32_t* r, uint32_t a) {
    asm volatile("ldmatrix.sync.aligned.m8n8.x4.trans.shared.b16 {%0,%1,%2,%3}, [%4];"
                 : "=r"(r[0]), "=r"(r[1]), "=r"(r[2]), "=r"(r[3]) : "r"(a));
}
__device__ __forceinline__ void mma16816h(float* d, const uint32_t* a, const uint32_t* b) {
    asm volatile("mma.sync.aligned.m16n8k16.row.col.f32.f16.f16.f32 "
                 "{%0,%1,%2,%3}, {%4,%5,%6,%7}, {%8,%9}, {%0,%1,%2,%3};"
                 : "+f"(d[0]), "+f"(d[1]), "+f"(d[2]), "+f"(d[3])
                 : "r"(a[0]), "r"(a[1]), "r"(a[2]), "r"(a[3]), "r"(b[0]), "r"(b[1]));
}
__device__ __forceinline__ void cpa16(uint32_t s, const void* g) {
    asm volatile("cp.async.cg.shared.global [%0], [%1], 16;" :: "r"(s), "l"(g) : "memory");
}
__device__ __forceinline__ uint32_t packh(float a, float b) {
    __half2 t = __floats2half2_rn(a, b);   // a in low half
    return *(uint32_t*)&t;
}

// smem tile geometry for hgemm: 128 rows x 64 halves, pitch 72 halves (144B)
#define LK2 72
#define TILE2B (128*LK2*2)      // 18432 B per tile
#define NSTG 3

// ==================== HMMA fp16 GEMM: C = A@B^T (+X) ====================
// MODE 0: C fp32   MODE 1: C = acc + X (fp32)   MODE 2: swiglu pairs -> O fp16
// MODE 3: O fp16 raw
template<int MODE>
__global__ void __launch_bounds__(256, 2)
hgemm(const __half* __restrict__ A, const __half* __restrict__ B,
      float* __restrict__ C, const float* __restrict__ X,
      __half* __restrict__ O, int K, int ldc) {
    extern __shared__ char smem[];
    uint32_t s0 = smem_u32(smem);

    int tid = threadIdx.x, lane = tid & 31, wid = tid >> 5;
    int m0 = blockIdx.y * 128, n0 = blockIdx.x * 128;
    int wm = wid & 1, wn = wid >> 1;     // 2 x 4 warps; warp tile 64(M) x 32(N)

    float acc[4][4][4];
    #pragma unroll
    for (int i = 0; i < 4; i++)
        #pragma unroll
        for (int j = 0; j < 4; j++)
            #pragma unroll
            for (int e = 0; e < 4; e++) acc[i][j][e] = 0.f;

    auto issue = [&](int slot, int kc) {
        uint32_t sa = s0 + slot * 2 * TILE2B;
        uint32_t sb = sa + TILE2B;
        #pragma unroll
        for (int t = 0; t < 4; ++t) {
            int idx = tid + t * 256;            // 1024 chunks per tile
            int r = idx >> 3, c = (idx & 7) * 8;
            cpa16(sa + (r * LK2 + c) * 2, A + (size_t)(m0 + r) * K + kc + c);
            cpa16(sb + (r * LK2 + c) * 2, B + (size_t)(n0 + r) * K + kc + c);
        }
        asm volatile("cp.async.commit_group;" ::: "memory");
    };

    int arow = wm * 64 + (lane & 15);
    int acol = (lane & 16) ? 8 : 0;
    int brow = wn * 32 + (lane & 7) + ((lane & 16) ? 8 : 0);
    int bcol = (lane & 8) ? 8 : 0;

    int NC = K >> 6;
    issue(0, 0);
    issue(1, 64);

    for (int c = 0; c < NC; ++c) {
        if (c + 1 < NC) {
            asm volatile("cp.async.wait_group 1;" ::: "memory");
        } else {
            asm volatile("cp.async.wait_group 0;" ::: "memory");
        }
        __syncthreads();      // single sync: data of stage c ready AND slot (c-1) free

        int slot = c % NSTG;
        uint32_t sA = s0 + slot * 2 * TILE2B;
        uint32_t sB = sA + TILE2B;

        #pragma unroll
        for (int ks = 0; ks < 4; ++ks) {
            uint32_t bf[2][4];
            #pragma unroll
            for (int ni2 = 0; ni2 < 2; ++ni2)
                ldsm4(bf[ni2], sB + ((brow + ni2 * 16) * LK2 + bcol + ks * 16) * 2);
            #pragma unroll
            for (int mi = 0; mi < 4; ++mi) {
                uint32_t af[4];
                ldsm4(af, sA + ((arow + mi * 16) * LK2 + acol + ks * 16) * 2);
                #pragma unroll
                for (int n8 = 0; n8 < 4; ++n8)
                    mma16816h(acc[mi][n8], af, &bf[n8 >> 1][(n8 & 1) * 2]);
            }
        }

        if (c + 2 < NC) issue((c + 2) % NSTG, (c + 2) << 6);
    }

    int rbase = m0 + wm * 64 + (lane >> 2);
    #pragma unroll
    for (int mi = 0; mi < 4; ++mi) {
        #pragma unroll
        for (int half = 0; half < 2; ++half) {
            int row = rbase + mi * 16 + half * 8;
            if (MODE == 2) {
                // swiglu: acc pairs (a,b) at cols (2p, 2p+1) -> g[row][p]
                int pldc = ldc >> 1;
                int pbase = (n0 >> 1) + wn * 16 + (lane & 3);
                #pragma unroll
                for (int n8 = 0; n8 < 4; ++n8) {
                    float a = acc[mi][n8][half * 2 + 0];
                    float b = acc[mi][n8][half * 2 + 1];
                    float g = a / (1.0f + expf(-a)) * b;
                    O[(size_t)row * pldc + pbase + n8 * 4] = __float2half(g);
                }
            } else if (MODE == 3) {
                int cbase = n0 + wn * 32 + (lane & 3) * 2;
                __half* orow = O + (size_t)row * ldc;
                #pragma unroll
                for (int n8 = 0; n8 < 4; ++n8) {
                    int col = cbase + n8 * 8;
                    *(uint32_t*)(orow + col) =
                        packh(acc[mi][n8][half * 2 + 0], acc[mi][n8][half * 2 + 1]);
                }
            } else {
                int cbase = n0 + wn * 32 + (lane & 3) * 2;
                float* crow = C + (size_t)row * ldc;
                const float* xrow = (MODE == 1) ? X + (size_t)row * ldc : nullptr;
                #pragma unroll
                for (int n8 = 0; n8 < 4; ++n8) {
                    int col = cbase + n8 * 8;
                    float2 v;
                    v.x = acc[mi][n8][half * 2 + 0];
                    v.y = acc[mi][n8][half * 2 + 1];
                    if (MODE == 1) {
                        float2 xv = *(const float2*)(xrow + col);
                        v.x += xv.x; v.y += xv.y;
                    }
                    *(float2*)(crow + col) = v;
                }
            }
        }
    }
}

// ==================== unified weight prep (one launch) ====================
__global__ void prep_all(const float* __restrict__ wq, const float* __restrict__ wk,
                         const float* __restrict__ wv, const float* __restrict__ wo,
                         const float* __restrict__ w1, const float* __restrict__ w2,
                         const float* __restrict__ w3,
                         __half* __restrict__ wqkv, __half* __restrict__ wot,
                         __half* __restrict__ w13,  __half* __restrict__ w2t) {
    int id = blockIdx.x;
    const float* W; __half* dst;
    int N, nb, roff = 0, ldo, inter = 0, odd = 0, local;
    if (id < 1024)      { W = wq; dst = wqkv; N = 1024; nb = 32; roff = 0;    ldo = 1024; local = id; }
    else if (id < 2048) { W = wk; dst = wqkv; N = 1024; nb = 32; roff = 1024; ldo = 1024; local = id - 1024; }
    else if (id < 3072) { W = wv; dst = wqkv; N = 1024; nb = 32; roff = 2048; ldo = 1024; local = id - 2048; }
    else if (id < 4096) { W = wo; dst = wot;  N = 1024; nb = 32; roff = 0;    ldo = 1024; local = id - 3072; }
    else if (id < 8192) { W = w1; dst = w13;  N = 4096; nb = 128; ldo = 1024; inter = 1; odd = 0; local = id - 4096; }
    else if (id < 12288){ W = w3; dst = w13;  N = 4096; nb = 128; ldo = 1024; inter = 1; odd = 1; local = id - 8192; }
    else                { W = w2; dst = w2t;  N = 1024; nb = 32;  ldo = 4096; local = id - 12288; }

    __shared__ float t[32][33];
    int tx = threadIdx.x, ty = threadIdx.y;     // 32 x 8
    int n0 = (local % nb) * 32, k0 = (local / nb) * 32;
    #pragma unroll
    for (int i = 0; i < 32; i += 8)
        t[ty + i][tx] = W[(size_t)(k0 + ty + i) * N + n0 + tx];
    __syncthreads();
    #pragma unroll
    for (int i = 0; i < 32; i += 8) {
        float v = t[tx][ty + i];
        int n = n0 + ty + i;
        int row = inter ? (2 * n + odd) : (roff + n);
        dst[(size_t)row * ldo + k0 + tx] = __float2half(v);
    }
}

// ==================== LayerNorm -> fp16 ====================
__global__ void ln_h(const float* __restrict__ x, const float* __restrict__ g,
                     const float* __restrict__ b, __half* __restrict__ y) {
    int t = blockIdx.x, tid = threadIdx.x;
    const float4* xr = (const float4*)(x + (size_t)t * D_);
    float4 xv = xr[tid];
    __shared__ float rbuf[8];
    __shared__ float s_mean, s_rstd;

    float s = xv.x + xv.y + xv.z + xv.w;
    #pragma unroll
    for (int o = 16; o; o >>= 1) s += __shfl_xor_sync(~0u, s, o);
    if ((tid & 31) == 0) rbuf[tid >> 5] = s;
    __syncthreads();
    if (tid == 0) {
        float m = 0.f;
        #pragma unroll
        for (int i = 0; i < 8; i++) m += rbuf[i];
        s_mean = m * (1.0f / D_);
    }
    __syncthreads();
    float mean = s_mean;
    float dx = xv.x - mean, dy = xv.y - mean, dz = xv.z - mean, dw = xv.w - mean;
    float s2 = dx*dx + dy*dy + dz*dz + dw*dw;
    #pragma unroll
    for (int o = 16; o; o >>= 1) s2 += __shfl_xor_sync(~0u, s2, o);
    if ((tid & 31) == 0) rbuf[tid >> 5] = s2;
    __syncthreads();
    if (tid == 0) {
        float v = 0.f;
        #pragma unroll
        for (int i = 0; i < 8; i++) v += rbuf[i];
        s_rstd = rsqrtf(v * (1.0f / D_) + 1e-6f);
    }
    __syncthreads();
    float rstd = s_rstd;
    const float4 gv = ((const float4*)g)[tid];
    const float4 bv = ((const float4*)b)[tid];
    size_t base = (size_t)t * D_ + tid * 4;
    y[base+0] = __float2half(dx * rstd * gv.x + bv.x);
    y[base+1] = __float2half(dy * rstd * gv.y + bv.y);
    y[base+2] = __float2half(dz * rstd * gv.z + bv.z);
    y[base+3] = __float2half(dw * rstd * gv.w + bv.w);
}

// ==================== RoPE table (double math, once) ====================
__global__ void build_tab(float2* __restrict__ tab) {
    int i = blockIdx.x * 256 + threadIdx.x;     // S*32
    int s = i >> 5, dd = i & 31;
    double inv = exp(-(double)dd * (log(10000.0) / 32.0));
    double ang = (double)s * inv;
    tab[i] = make_float2((float)cos(ang), (float)sin(ang));
}

// ==================== RoPE + scatter: qkv fp16 -> q/k/v fp16 [b,h,s,d] ====================
__global__ void rope_cvt(const __half* __restrict__ qkv, const float2* __restrict__ tab,
                         __half* __restrict__ qh, __half* __restrict__ kh,
                         __half* __restrict__ vh) {
    int t = blockIdx.x;                 // token
    int tid = threadIdx.x;              // 128
    int b = t / S_, s = t & (S_ - 1);
    int d = tid & 63;
    float2 cs = tab[s * 32 + (d & 31)];
    float c = cs.x, sn = cs.y;
    const __half* row = qkv + (size_t)t * QKV_LD;

    #pragma unroll
    for (int hh = 0; hh < 8; ++hh) {
        int h = hh * 2 + (tid >> 6);
        size_t oidx = ((size_t)(b * H_ + h) * S_ + s) * HD_ + d;
        {
            float x1 = __half2float(row[h * 64 + d]);
            float x2 = __half2float(row[h * 64 + (d ^ 32)]);
            float o = (d < 32) ? (x1 * c - x2 * sn) : (x1 * c + x2 * sn);
            qh[oidx] = __float2half(o * 0.125f);
        }
        {
            float x1 = __half2float(row[1024 + h * 64 + d]);
            float x2 = __half2float(row[1024 + h * 64 + (d ^ 32)]);
            float o = (d < 32) ? (x1 * c - x2 * sn) : (x1 * c + x2 * sn);
            kh[oidx] = __float2half(o);
        }
        vh[oidx] = row[2048 + h * 64 + d];
    }
}

// ==================== flash attention (HMMA fp16, sliding window 256) ====================
#define LK_ 72
__global__ void __launch_bounds__(256, 2)
attn_mma(const __half* __restrict__ qh, const __half* __restrict__ kh,
         const __half* __restrict__ vh, __half* __restrict__ ch) {
    extern __shared__ char smem[];
    uint32_t sQ = smem_u32(smem);
    uint32_t sK = sQ + 128 * LK_ * 2;
    uint32_t sV = sK + 128 * LK_ * 2;

    int q0 = blockIdx.x * 128;
    int h = blockIdx.y, bi = blockIdx.z;
    int tid = threadIdx.x, lane = tid & 31, w = tid >> 5;
    size_t bh = ((size_t)(bi * H_ + h)) * S_;

    for (int i = tid; i < 128 * 8; i += 256) {
        int r = i >> 3, c8 = (i & 7) * 8;
        uint4 v = *(const uint4*)(qh + (bh + q0 + r) * HD_ + c8);
        *(uint4*)(smem + (r * LK_ + c8) * 2) = v;
    }
    __syncthreads();

    uint32_t qf[4][4];
    {
        int ar = w * 16 + (lane & 15);
        int ac = (lane & 16) ? 8 : 0;
        #pragma unroll
        for (int kc = 0; kc < 4; ++kc)
            ldsm4(qf[kc], sQ + (ar * LK_ + ac + kc * 16) * 2);
    }

    float O[8][4];
    #pragma unroll
    for (int i = 0; i < 8; i++) { O[i][0]=0; O[i][1]=0; O[i][2]=0; O[i][3]=0; }
    float rm0 = -1e30f, rm1 = -1e30f, l0 = 0.f, l1 = 0.f;

    int g = lane >> 2, tq = lane & 3;
    int qrow0 = q0 + w * 16 + g;

    #pragma unroll
    for (int it = 0; it < 3; ++it) {
        int ord = 2 - it;                    // diagonal tile first
        int kbase = q0 - 256 + ord * 128;
        if (kbase + 128 <= 0) continue;

        __syncthreads();
        for (int i = tid; i < 128 * 8; i += 256) {
            int r = i >> 3, c8 = (i & 7) * 8;
            int krow = kbase + r; if (krow < 0) krow = 0;
            uint4 kv = *(const uint4*)(kh + (bh + krow) * HD_ + c8);
            uint4 vv = *(const uint4*)(vh + (bh + krow) * HD_ + c8);
            *(uint4*)(smem + (128 * LK_ + r * LK_ + c8) * 2) = kv;
            *(uint4*)(smem + (256 * LK_ + r * LK_ + c8) * 2) = vv;
        }
        __syncthreads();

        float sf[16][4];
        {
            int br = (lane & 7) + ((lane & 16) ? 8 : 0);
            int bc = (lane & 8) ? 8 : 0;
            #pragma unroll
            for (int ni2 = 0; ni2 < 8; ++ni2) {
                float s4[8] = {0,0,0,0,0,0,0,0};
                #pragma unroll
                for (int kc = 0; kc < 4; ++kc) {
                    uint32_t kf[4];
                    ldsm4(kf, sK + ((ni2 * 16 + br) * LK_ + bc + kc * 16) * 2);
                    mma16816h(s4,     qf[kc], kf + 0);
                    mma16816h(s4 + 4, qf[kc], kf + 2);
                }
                #pragma unroll
                for (int e = 0; e < 4; e++) { sf[2*ni2][e] = s4[e]; sf[2*ni2+1][e] = s4[4+e]; }
            }
        }

        float tm0 = -1e30f, tm1 = -1e30f;
        #pragma unroll
        for (int ni = 0; ni < 16; ++ni) {
            int colb = kbase + ni * 8 + tq * 2;
            #pragma unroll
            for (int e = 0; e < 2; ++e) {
                int col = colb + e;
                int r0 = qrow0 - col, r1 = qrow0 + 8 - col;
                if (!(col >= 0 && r0 >= 0 && r0 < W_)) sf[ni][e]     = -1e30f;
                if (!(col >= 0 && r1 >= 0 && r1 < W_)) sf[ni][2 + e] = -1e30f;
                tm0 = fmaxf(tm0, sf[ni][e]);
                tm1 = fmaxf(tm1, sf[ni][2 + e]);
            }
        }
        tm0 = fmaxf(tm0, __shfl_xor_sync(~0u, tm0, 1));
        tm0 = fmaxf(tm0, __shfl_xor_sync(~0u, tm0, 2));
        tm1 = fmaxf(tm1, __shfl_xor_sync(~0u, tm1, 1));
        tm1 = fmaxf(tm1, __shfl_xor_sync(~0u, tm1, 2));

        float m0 = fmaxf(rm0, tm0), m1 = fmaxf(rm1, tm1);
        float a0 = __expf(rm0 - m0), a1 = __expf(rm1 - m1);
        rm0 = m0; rm1 = m1;
        #pragma unroll
        for (int nd = 0; nd < 8; ++nd) {
            O[nd][0] *= a0; O[nd][1] *= a0; O[nd][2] *= a1; O[nd][3] *= a1;
        }
        float rs0 = 0.f, rs1 = 0.f;
        #pragma unroll
        for (int ni = 0; ni < 16; ++ni) {
            float p0 = __expf(sf[ni][0] - m0);
            float p1 = __expf(sf[ni][1] - m0);
            float p2 = __expf(sf[ni][2] - m1);
            float p3 = __expf(sf[ni][3] - m1);
            sf[ni][0] = p0; sf[ni][1] = p1; sf[ni][2] = p2; sf[ni][3] = p3;
            rs0 += p0 + p1; rs1 += p2 + p3;
        }
        rs0 += __shfl_xor_sync(~0u, rs0, 1); rs0 += __shfl_xor_sync(~0u, rs0, 2);
        rs1 += __shfl_xor_sync(~0u, rs1, 1); rs1 += __shfl_xor_sync(~0u, rs1, 2);
        l0 = l0 * a0 + rs0;
        l1 = l1 * a1 + rs1;

        #pragma unroll
        for (int j = 0; j < 8; ++j) {
            uint32_t aP[4];
            aP[0] = packh(sf[2*j][0],   sf[2*j][1]);
            aP[1] = packh(sf[2*j][2],   sf[2*j][3]);
            aP[2] = packh(sf[2*j+1][0], sf[2*j+1][1]);
            aP[3] = packh(sf[2*j+1][2], sf[2*j+1][3]);
            int sel = lane >> 3;
            int vr = 16 * j + (lane & 7) + ((sel & 1) * 8);
            #pragma unroll
            for (int np = 0; np < 4; ++np) {
                uint32_t vf[4];
                ldsm4t(vf, sV + (vr * LK_ + np * 16 + ((sel >> 1) * 8)) * 2);
                mma16816h(O[2*np],     aP, vf + 0);
                mma16816h(O[2*np + 1], aP, vf + 2);
            }
        }
    }

    float i0 = 1.0f / l0, i1 = 1.0f / l1;
    size_t r0o = ((size_t)(bi * S_ + qrow0)) * D_ + h * HD_;
    size_t r1o = ((size_t)(bi * S_ + qrow0 + 8)) * D_ + h * HD_;
    #pragma unroll
    for (int nd = 0; nd < 8; ++nd) {
        int col = nd * 8 + tq * 2;
        #pragma unroll
        for (int e = 0; e < 2; ++e) {
            ch[r0o + col + e] = __float2half(O[nd][e] * i0);
            ch[r1o + col + e] = __float2half(O[nd][2 + e] * i1);
        }
    }
}

// ==================== launch ====================
extern "C" void kernel_launch(void* const* d_in, const int* in_sizes, int n_in,
                              void* d_out, int out_size) {
    const float* hidden = (const float*)d_in[0];
    const float* wq = (const float*)d_in[1];
    const float* wk = (const float*)d_in[2];
    const float* wv = (const float*)d_in[3];
    const float* wo = (const float*)d_in[4];
    const float* w1 = (const float*)d_in[5];
    const float* w2 = (const float*)d_in[6];
    const float* w3 = (const float*)d_in[7];
    const float* ln1_g = (const float*)d_in[8];
    const float* ln1_b = (const float*)d_in[9];
    const float* ln2_g = (const float*)d_in[10];
    const float* ln2_b = (const float*)d_in[11];
    float* out = (float*)d_out;

    float *hid; float2* tab;
    __half *qkvh, *xa, *ca, *gg, *qh, *kh, *vh, *wqkv, *wot, *w13, *w2t;
    cudaGetSymbolAddress((void**)&hid, g_hid);
    cudaGetSymbolAddress((void**)&tab, g_tab);
    cudaGetSymbolAddress((void**)&qkvh, g_qkvh);
    cudaGetSymbolAddress((void**)&xa, g_xa);
    cudaGetSymbolAddress((void**)&ca, g_ca);
    cudaGetSymbolAddress((void**)&gg, g_g);
    cudaGetSymbolAddress((void**)&qh, g_qh);
    cudaGetSymbolAddress((void**)&kh, g_kh);
    cudaGetSymbolAddress((void**)&vh, g_vh);
    cudaGetSymbolAddress((void**)&wqkv, g_wqkv);
    cudaGetSymbolAddress((void**)&wot, g_wot);
    cudaGetSymbolAddress((void**)&w13, g_w13);
    cudaGetSymbolAddress((void**)&w2t, g_w2t);

    const int SMEM_G = 2 * NSTG * TILE2B;      // 110592 B (3 stages x A,B)
    cudaFuncSetAttribute(hgemm<1>, cudaFuncAttributeMaxDynamicSharedMemorySize, SMEM_G);
    cudaFuncSetAttribute(hgemm<2>, cudaFuncAttributeMaxDynamicSharedMemorySize, SMEM_G);
    cudaFuncSetAttribute(hgemm<3>, cudaFuncAttributeMaxDynamicSharedMemorySize, SMEM_G);
    const int SMEM_ATT = 3 * 128 * LK_ * 2;   // 55296 B
    cudaFuncSetAttribute(attn_mma, cudaFuncAttributeMaxDynamicSharedMemorySize, SMEM_ATT);

    build_tab<<<(S_ * 32) / 256, 256>>>(tab);
    prep_all<<<16384, dim3(32, 8)>>>(wq, wk, wv, wo, w1, w2, w3, wqkv, wot, w13, w2t);

    // --- attention sub-block ---
    ln_h<<<TOK, 256>>>(hidden, ln1_g, ln1_b, xa);
    hgemm<3><<<dim3(24, 32), 256, SMEM_G>>>(xa, wqkv, nullptr, nullptr, qkvh, 1024, QKV_LD);
    rope_cvt<<<TOK, 128>>>(qkvh, tab, qh, kh, vh);
    attn_mma<<<dim3(S_ / 128, H_, B_), 256, SMEM_ATT>>>(qh, kh, vh, ca);
    hgemm<1><<<dim3(8, 32), 256, SMEM_G>>>(ca, wot, hid, hidden, nullptr, 1024, D_);

    // --- SwiGLU MLP sub-block ---
    ln_h<<<TOK, 256>>>(hid, ln2_g, ln2_b, xa);
    hgemm<2><<<dim3(64, 32), 256, SMEM_G>>>(xa, w13, nullptr, nullptr, gg, 1024, 8192);
    hgemm<1><<<dim3(8, 32), 256, SMEM_G>>>(gg, w2t, out, hid, nullptr, 4096, D_);
}